// round 11
// baseline (speedup 1.0000x reference)
#include <cuda_runtime.h>
#include <math.h>
#include <stdint.h>

// Problem dims
#define B_   32
#define N_   3136
#define C_   384
#define H_   8
#define DH_  48
#define M_   196
#define T_   (B_ * N_)          // 100352 tokens

// ---------------- scratch (static device globals; no runtime allocation) ---
__device__ float g_xg[T_ * C_];              // gelu(ln(x)), tf32-valued
__device__ float g_k [B_ * H_ * N_ * DH_];   // k [b,h,n,d], tf32-valued
__device__ float g_v [B_ * H_ * N_ * DH_];   // v [b,h,n,d], tf32-valued
__device__ float g_ao[B_ * M_ * C_];         // attn out [b,m,c], tf32-valued
__device__ float g_wkv[2 * C_ * C_];         // kv_w pre-rounded to tf32
__device__ float g_wpj[C_ * C_];             // proj_w pre-rounded to tf32

// ------------------------------------------------------ tf32 helpers
__device__ __forceinline__ unsigned f2tf32(float f) {
    unsigned r;
    asm("cvt.rna.tf32.f32 %0, %1;" : "=r"(r) : "f"(f));
    return r;
}
__device__ __forceinline__ float rtf32(float f) { return __uint_as_float(f2tf32(f)); }

__device__ __forceinline__ void mma_tf32(float* c, const unsigned* a, const unsigned* b) {
    asm volatile(
        "mma.sync.aligned.m16n8k8.row.col.f32.tf32.tf32.f32 "
        "{%0,%1,%2,%3}, {%4,%5,%6,%7}, {%8,%9}, {%0,%1,%2,%3};"
        : "+f"(c[0]), "+f"(c[1]), "+f"(c[2]), "+f"(c[3])
        : "r"(a[0]), "r"(a[1]), "r"(a[2]), "r"(a[3]),
          "r"(b[0]), "r"(b[1]));
}

// ldmatrix x4 on 32-bit (tf32) data viewed as b16 pairs:
// per 8x4(32-bit) tile, thread t gets element (row t/4, col t%4).
__device__ __forceinline__ void ldsm_x4(unsigned &r0, unsigned &r1,
                                        unsigned &r2, unsigned &r3, uint32_t addr) {
    asm volatile("ldmatrix.sync.aligned.m8n8.x4.shared.b16 {%0,%1,%2,%3}, [%4];"
        : "=r"(r0), "=r"(r1), "=r"(r2), "=r"(r3) : "r"(addr));
}

__device__ __forceinline__ void cp16(uint32_t sa, const void* g) {
    asm volatile("cp.async.cg.shared.global [%0], [%1], 16;" :: "r"(sa), "l"(g));
}
#define CP_COMMIT() asm volatile("cp.async.commit_group;")
#define CP_WAIT1()  asm volatile("cp.async.wait_group 1;")
#define CP_WAIT0()  asm volatile("cp.async.wait_group 0;")

// ------------------------------------------------- K0: pre-round weights
__global__ __launch_bounds__(256) void round_w_kernel(
    const float* __restrict__ kv_w, const float* __restrict__ proj_w)
{
    int i = blockIdx.x * 256 + threadIdx.x;
    if (i < 2 * C_ * C_) g_wkv[i] = rtf32(kv_w[i]);
    if (i < C_ * C_)     g_wpj[i] = rtf32(proj_w[i]);
}

// ---------------------------------------------------------------- K1: LN+GELU
__global__ __launch_bounds__(256) void ln_gelu_kernel(
    const float* __restrict__ x,
    const float* __restrict__ lw,
    const float* __restrict__ lb)
{
    int t = (blockIdx.x * 256 + threadIdx.x) >> 5;
    int lane = threadIdx.x & 31;
    const float4* xr = (const float4*)(x + (size_t)t * C_);
    float4* outr = (float4*)(g_xg + (size_t)t * C_);

    float4 a = xr[lane], bq = xr[lane + 32], cq = xr[lane + 64];
    float s = a.x + a.y + a.z + a.w + bq.x + bq.y + bq.z + bq.w
            + cq.x + cq.y + cq.z + cq.w;
    float q = a.x*a.x + a.y*a.y + a.z*a.z + a.w*a.w
            + bq.x*bq.x + bq.y*bq.y + bq.z*bq.z + bq.w*bq.w
            + cq.x*cq.x + cq.y*cq.y + cq.z*cq.z + cq.w*cq.w;
    #pragma unroll
    for (int o = 16; o > 0; o >>= 1) {
        s += __shfl_xor_sync(0xffffffffu, s, o);
        q += __shfl_xor_sync(0xffffffffu, q, o);
    }
    float mu  = s * (1.0f / C_);
    float var = q * (1.0f / C_) - mu * mu;
    float rs  = rsqrtf(var + 1e-6f);

    const float4* lw4 = (const float4*)lw;
    const float4* lb4 = (const float4*)lb;
    #pragma unroll
    for (int j = 0; j < 3; j++) {
        float4 v = (j == 0) ? a : ((j == 1) ? bq : cq);
        float4 w = lw4[lane + j * 32];
        float4 bb = lb4[lane + j * 32];
        float4 o;
        float y;
        y = (v.x - mu) * rs * w.x + bb.x;
        o.x = rtf32(0.5f * y * (1.0f + erff(y * 0.70710678118654752f)));
        y = (v.y - mu) * rs * w.y + bb.y;
        o.y = rtf32(0.5f * y * (1.0f + erff(y * 0.70710678118654752f)));
        y = (v.z - mu) * rs * w.z + bb.z;
        o.z = rtf32(0.5f * y * (1.0f + erff(y * 0.70710678118654752f)));
        y = (v.w - mu) * rs * w.w + bb.w;
        o.w = rtf32(0.5f * y * (1.0f + erff(y * 0.70710678118654752f)));
        outr[lane + j * 32] = o;
    }
}

// ============= shared 3-stage pipelined tf32 GEMM core (128x128 CTA) =========
// A,B tiles [row][k], tf32-exact values, ldmatrix fragment loads.
#define GSTRIDE 20
#define GSTAGEW (128 * GSTRIDE)
#define GBOFF   (3 * GSTAGEW)
#define GSMEMB  (6 * GSTAGEW * 4)

__device__ __forceinline__ void gemm_cp_chunk(
    float* sm, int stage, int tid, const float* Abase, const float* Bbase, int c)
{
    float* as = sm + stage * GSTAGEW;
    float* bs = sm + GBOFF + stage * GSTAGEW;
    #pragma unroll
    for (int j = 0; j < 2; j++) {
        int cidx = tid + j * 256;
        int row = cidx >> 2, kq = cidx & 3;
        cp16((uint32_t)__cvta_generic_to_shared(as + row * GSTRIDE + kq * 4),
             Abase + (size_t)row * C_ + c * 16 + kq * 4);
        cp16((uint32_t)__cvta_generic_to_shared(bs + row * GSTRIDE + kq * 4),
             Bbase + (size_t)row * C_ + c * 16 + kq * 4);
    }
    CP_COMMIT();
}

__device__ __forceinline__ void gemm_mainloop(
    float* sm, int tid, const float* Abase, const float* Bbase,
    float acc[4][4][4], int wm, int wn, int fr, int fk)
{
    int lane = tid & 31;
    int g = lane >> 3, lr = lane & 7;
    int row_add = ((g >> 1) << 3) + lr;   // +8 rows for tiles 2,3
    int k_add   = (g & 1) * 4;            // +4 k-words for tiles 1,3
    uint32_t sbase = (uint32_t)__cvta_generic_to_shared(sm);
    uint32_t a_addr0 = sbase + ((wm * 64 + row_add) * GSTRIDE + k_add) * 4;
    uint32_t b_addr0 = sbase + GBOFF * 4 + ((wn * 32 + row_add) * GSTRIDE + k_add) * 4;

    gemm_cp_chunk(sm, 0, tid, Abase, Bbase, 0);
    gemm_cp_chunk(sm, 1, tid, Abase, Bbase, 1);

    for (int c = 0; c < 24; c++) {
        if (c >= 22) { CP_WAIT0(); } else { CP_WAIT1(); }
        __syncthreads();
        uint32_t soff = (uint32_t)((c % 3) * GSTAGEW * 4);

        #pragma unroll
        for (int kp = 0; kp < 16; kp += 8) {
            unsigned af[4][4];
            #pragma unroll
            for (int mt = 0; mt < 4; mt++)
                ldsm_x4(af[mt][0], af[mt][2], af[mt][1], af[mt][3],
                        a_addr0 + soff + (uint32_t)((mt * 16 * GSTRIDE + kp) * 4));
            unsigned bf[4][2];
            #pragma unroll
            for (int j = 0; j < 2; j++)
                ldsm_x4(bf[2 * j][0], bf[2 * j][1], bf[2 * j + 1][0], bf[2 * j + 1][1],
                        b_addr0 + soff + (uint32_t)((j * 16 * GSTRIDE + kp) * 4));
            #pragma unroll
            for (int mt = 0; mt < 4; mt++)
                #pragma unroll
                for (int nt = 0; nt < 4; nt++)
                    mma_tf32(acc[mt][nt], af[mt], bf[nt]);
        }

        if (c + 2 < 24)
            gemm_cp_chunk(sm, (c + 2) % 3, tid, Abase, Bbase, c + 2);
    }
}

// --------------------------------------------------------- K2: kv GEMM (tf32)
__global__ void __launch_bounds__(256, 2) mma_kv_kernel()
{
    extern __shared__ float sm[];
    int n0 = blockIdx.x * 128;
    int m0 = blockIdx.y * 128;
    int tid = threadIdx.x;
    int wid = tid >> 5, lane = tid & 31;
    int wm = wid >> 2, wn = wid & 3;
    int fr = lane >> 2, fk = lane & 3;

    float acc[4][4][4];
    #pragma unroll
    for (int i = 0; i < 4; i++)
        #pragma unroll
        for (int j = 0; j < 4; j++)
            #pragma unroll
            for (int r = 0; r < 4; r++) acc[i][j][r] = 0.0f;

    gemm_mainloop(sm, tid, g_xg + (size_t)m0 * C_, g_wkv + (size_t)n0 * C_,
                  acc, wm, wn, fr, fk);

    #pragma unroll
    for (int mt = 0; mt < 4; mt++) {
        #pragma unroll
        for (int half = 0; half < 2; half++) {
            int r  = m0 + wm * 64 + mt * 16 + fr + half * 8;
            int bb = r / N_;
            int nn = r - bb * N_;
            #pragma unroll
            for (int nt = 0; nt < 4; nt++) {
                int c  = n0 + wn * 32 + nt * 8 + fk * 2;
                int cc = (c >= C_) ? (c - C_) : c;
                int h  = cc / DH_;
                int d  = cc - h * DH_;
                float* dst = (c >= C_) ? g_v : g_k;
                float2 val;
                val.x = rtf32(acc[mt][nt][half * 2 + 0]);
                val.y = rtf32(acc[mt][nt][half * 2 + 1]);
                *(float2*)(dst + (((size_t)bb * H_ + h) * N_ + nn) * DH_ + d) = val;
            }
        }
    }
}

// -------------------------------------------------------------- K4: proj GEMM
__global__ void __launch_bounds__(256, 2) mma_proj_kernel(
    const float* __restrict__ bias,
    float* __restrict__ out)
{
    extern __shared__ float sm[];
    int n0 = blockIdx.x * 128;
    int m0 = blockIdx.y * 128;
    int tid = threadIdx.x;
    int wid = tid >> 5, lane = tid & 31;
    int wm = wid >> 2, wn = wid & 3;
    int fr = lane >> 2, fk = lane & 3;

    float acc[4][4][4];
    #pragma unroll
    for (int i = 0; i < 4; i++)
        #pragma unroll
        for (int j = 0; j < 4; j++)
            #pragma unroll
            for (int r = 0; r < 4; r++) acc[i][j][r] = 0.0f;

    gemm_mainloop(sm, tid, g_ao + (size_t)m0 * C_, g_wpj + (size_t)n0 * C_,
                  acc, wm, wn, fr, fk);

    #pragma unroll
    for (int mt = 0; mt < 4; mt++) {
        #pragma unroll
        for (int half = 0; half < 2; half++) {
            int r = m0 + wm * 64 + mt * 16 + fr + half * 8;
            #pragma unroll
            for (int nt = 0; nt < 4; nt++) {
                int c = n0 + wn * 32 + nt * 8 + fk * 2;
                float2 val;
                val.x = acc[mt][nt][half * 2 + 0] + bias[c];
                val.y = acc[mt][nt][half * 2 + 1] + bias[c + 1];
                *(float2*)(out + (size_t)r * C_ + c) = val;
            }
        }
    }
}

// ------------------------------------------------------------- K3: MMA attn
// 13 warps (416 thr), one 16-row M-tile per warp, 2 CTAs/SM.
#define AT_THREADS 416
#define QROWS 208
#define QS_STRIDE 52
#define KS_OFF 10816
#define KS_STRIDE 52
#define KS_BUFW 3328
#define VS_OFF 17472
#define VS_STRIDE 56
#define VS_BUFW 3584
#define PS_OFF 24640
#define PS_STRIDE 12
#define AT_SMEMW 27712

__global__ void __launch_bounds__(AT_THREADS, 2) attn_mma_kernel(const float* __restrict__ qp)
{
    extern __shared__ uint32_t smv[];
    int tid = threadIdx.x;
    int bh = blockIdx.x;
    int b = bh >> 3, h = bh & 7;
    int wid = tid >> 5, lane = tid & 31;
    int fr = lane >> 2, fk = lane & 3;
    int g = lane >> 3, lr = lane & 7;

    const float* kbase = g_k + (size_t)bh * N_ * DH_;
    const float* vbase = g_v + (size_t)bh * N_ * DH_;

    for (int idx = tid; idx < QROWS * 48; idx += AT_THREADS) {
        int m = idx / 48, d = idx - m * 48;
        float v = (m < M_) ? qp[((size_t)m * H_ + h) * DH_ + d] : 0.0f;
        smv[m * QS_STRIDE + d] = f2tf32(v);
    }

    for (int cidx = tid; cidx < 768; cidx += AT_THREADS) {
        int r = cidx / 12, cc = cidx - r * 12;
        cp16((uint32_t)__cvta_generic_to_shared(smv + KS_OFF + r * KS_STRIDE + cc * 4),
             (const float4*)kbase + cidx);
        cp16((uint32_t)__cvta_generic_to_shared(smv + VS_OFF + r * VS_STRIDE + cc * 4),
             (const float4*)vbase + cidx);
    }
    CP_COMMIT();
    __syncthreads();

    unsigned qf[6][4];
    {
        int r0 = wid * 16 + fr;
        #pragma unroll
        for (int kt = 0; kt < 6; kt++) {
            qf[kt][0] = smv[r0 * QS_STRIDE + kt * 8 + fk];
            qf[kt][1] = smv[(r0 + 8) * QS_STRIDE + kt * 8 + fk];
            qf[kt][2] = smv[r0 * QS_STRIDE + kt * 8 + fk + 4];
            qf[kt][3] = smv[(r0 + 8) * QS_STRIDE + kt * 8 + fk + 4];
        }
    }

    float oacc[6][4];
    #pragma unroll
    for (int j = 0; j < 6; j++)
        #pragma unroll
        for (int r = 0; r < 4; r++) oacc[j][r] = 0.0f;
    float lsum[2] = {0.f, 0.f};

    uint32_t ps_base = PS_OFF + wid * 16 * PS_STRIDE;
    uint32_t sm_sh = (uint32_t)__cvta_generic_to_shared(smv);
    // per-thread ldmatrix column offset for K-frags (row = key, col = d-words)
    uint32_t kcol_off = (uint32_t)(((g >> 1) * 8 + (g & 1) * 4) * 4);

    for (int c = 0; c < 49; c++) {
        int buf = c & 1;
        if (c + 1 < 49) {
            int nb = buf ^ 1;
            const float4* ks = (const float4*)(kbase + (size_t)(c + 1) * 64 * DH_);
            const float4* vs = (const float4*)(vbase + (size_t)(c + 1) * 64 * DH_);
            for (int cidx = tid; cidx < 768; cidx += AT_THREADS) {
                int r = cidx / 12, cc2 = cidx - r * 12;
                cp16((uint32_t)__cvta_generic_to_shared(
                         smv + KS_OFF + nb * KS_BUFW + r * KS_STRIDE + cc2 * 4),
                     ks + cidx);
                cp16((uint32_t)__cvta_generic_to_shared(
                         smv + VS_OFF + nb * VS_BUFW + r * VS_STRIDE + cc2 * 4),
                     vs + cidx);
            }
            CP_COMMIT();
            CP_WAIT1();
        } else {
            CP_WAIT0();
        }
        __syncthreads();

        uint32_t kb_sh = sm_sh + (uint32_t)((KS_OFF + buf * KS_BUFW) * 4);
        const uint32_t* vb = smv + VS_OFF + buf * VS_BUFW;

        for (int sub = 0; sub < 8; sub++) {
            // ---- QK: K-frags via ldmatrix (rows = 8 keys of sub) ----
            float s0[4] = {0.f, 0.f, 0.f, 0.f};
            uint32_t krow = kb_sh + (uint32_t)(((sub * 8 + lr) * KS_STRIDE) * 4) + kcol_off;
            #pragma unroll
            for (int jp = 0; jp < 3; jp++) {
                unsigned bk0[2], bk1[2];
                ldsm_x4(bk0[0], bk0[1], bk1[0], bk1[1],
                        krow + (uint32_t)(jp * 64));   // 16 words per kt-pair
                mma_tf32(s0, qf[2 * jp], bk0);
                mma_tf32(s0, qf[2 * jp + 1], bk1);
            }
            // ---- exp + P store + lsum ----
            {
                unsigned c0 = f2tf32(__expf(s0[0]));
                unsigned c1 = f2tf32(__expf(s0[1]));
                unsigned c2 = f2tf32(__expf(s0[2]));
                unsigned c3 = f2tf32(__expf(s0[3]));
                lsum[0] += __uint_as_float(c0) + __uint_as_float(c1);
                lsum[1] += __uint_as_float(c2) + __uint_as_float(c3);
                uint32_t a0 = ps_base + fr * PS_STRIDE + 2 * fk;
                smv[a0] = c0; smv[a0 + 1] = c1;
                uint32_t a1 = ps_base + (fr + 8) * PS_STRIDE + 2 * fk;
                smv[a1] = c2; smv[a1 + 1] = c3;
            }
            __syncwarp();
            unsigned pa[4];
            pa[0] = smv[ps_base + fr * PS_STRIDE + fk];
            pa[1] = smv[ps_base + (fr + 8) * PS_STRIDE + fk];
            pa[2] = smv[ps_base + fr * PS_STRIDE + fk + 4];
            pa[3] = smv[ps_base + (fr + 8) * PS_STRIDE + fk + 4];
            __syncwarp();
            // ---- PV (V scalar loads; transposed access, no ldmatrix) ----
            #pragma unroll
            for (int nt = 0; nt < 6; nt++) {
                unsigned vv[2];
                vv[0] = vb[(sub * 8 + fk) * VS_STRIDE + nt * 8 + fr];
                vv[1] = vb[(sub * 8 + fk + 4) * VS_STRIDE + nt * 8 + fr];
                mma_tf32(oacc[nt], pa, vv);
            }
        }
        __syncthreads();
    }

    // ---- epilogue ----
    #pragma unroll
    for (int hh = 0; hh < 2; hh++) {
        float l = lsum[hh];
        l += __shfl_xor_sync(0xffffffffu, l, 1);
        l += __shfl_xor_sync(0xffffffffu, l, 2);
        float inv = 1.0f / l;
        int m = wid * 16 + fr + hh * 8;
        if (m < M_) {
            float* orow = g_ao + ((size_t)b * M_ + m) * C_ + h * DH_;
            #pragma unroll
            for (int nt = 0; nt < 6; nt++) {
                float2 val;
                val.x = rtf32(oacc[nt][hh * 2 + 0] * inv);
                val.y = rtf32(oacc[nt][hh * 2 + 1] * inv);
                *(float2*)(orow + nt * 8 + 2 * fk) = val;
            }
        }
    }
}

// ----------------------------------------------------------------- launcher
extern "C" void kernel_launch(void* const* d_in, const int* in_sizes, int n_in,
                              void* d_out, int out_size)
{
    const float* x      = (const float*)d_in[0];
    const float* qp     = (const float*)d_in[1];
    const float* kv_w   = (const float*)d_in[2];
    const float* proj_w = (const float*)d_in[3];
    const float* proj_b = (const float*)d_in[4];
    const float* ln_w   = (const float*)d_in[5];
    const float* ln_b   = (const float*)d_in[6];
    float* out = (float*)d_out;

    cudaFuncSetAttribute(attn_mma_kernel,
                         cudaFuncAttributeMaxDynamicSharedMemorySize, AT_SMEMW * 4);
    cudaFuncSetAttribute(mma_kv_kernel,
                         cudaFuncAttributeMaxDynamicSharedMemorySize, GSMEMB);
    cudaFuncSetAttribute(mma_proj_kernel,
                         cudaFuncAttributeMaxDynamicSharedMemorySize, GSMEMB);

    round_w_kernel<<<(2 * C_ * C_ + 255) / 256, 256>>>(kv_w, proj_w);

    ln_gelu_kernel<<<T_ / 8, 256>>>(x, ln_w, ln_b);

    dim3 g2(6, 784);
    mma_kv_kernel<<<g2, 256, GSMEMB>>>();

    attn_mma_kernel<<<B_ * H_, AT_THREADS, AT_SMEMW * 4>>>(qp);

    dim3 g4(3, 49);
    mma_proj_kernel<<<g4, 256, GSMEMB>>>(proj_b, out);
}

// round 12
// speedup vs baseline: 1.1026x; 1.1026x over previous
#include <cuda_runtime.h>
#include <math.h>
#include <stdint.h>

// Problem dims
#define B_   32
#define N_   3136
#define C_   384
#define H_   8
#define DH_  48
#define M_   196
#define T_   (B_ * N_)          // 100352 tokens

// ---------------- scratch (static device globals; no runtime allocation) ---
__device__ float g_xg[T_ * C_];              // gelu(ln(x)), tf32-valued
__device__ float g_k [B_ * H_ * N_ * DH_];   // k [b,h,n,d], tf32-valued
__device__ float g_v [B_ * H_ * N_ * DH_];   // v [b,h,n,d], tf32-valued
__device__ float g_ao[B_ * M_ * C_];         // attn out [b,m,c], tf32-valued
__device__ float g_wkv[2 * C_ * C_];         // kv_w pre-rounded to tf32
__device__ float g_wpj[C_ * C_];             // proj_w pre-rounded to tf32

// ------------------------------------------------------ tf32 helpers
__device__ __forceinline__ unsigned f2tf32(float f) {
    unsigned r;
    asm("cvt.rna.tf32.f32 %0, %1;" : "=r"(r) : "f"(f));
    return r;
}
__device__ __forceinline__ float rtf32(float f) { return __uint_as_float(f2tf32(f)); }

__device__ __forceinline__ void mma_tf32(float* c, const unsigned* a, const unsigned* b) {
    asm volatile(
        "mma.sync.aligned.m16n8k8.row.col.f32.tf32.tf32.f32 "
        "{%0,%1,%2,%3}, {%4,%5,%6,%7}, {%8,%9}, {%0,%1,%2,%3};"
        : "+f"(c[0]), "+f"(c[1]), "+f"(c[2]), "+f"(c[3])
        : "r"(a[0]), "r"(a[1]), "r"(a[2]), "r"(a[3]),
          "r"(b[0]), "r"(b[1]));
}

// ldmatrix x4 on 32-bit (tf32) data viewed as b16 pairs (attn K-frags only):
// per 8x4(32-bit) tile, thread t gets element (row t/4, col t%4).
__device__ __forceinline__ void ldsm_x4(unsigned &r0, unsigned &r1,
                                        unsigned &r2, unsigned &r3, uint32_t addr) {
    asm volatile("ldmatrix.sync.aligned.m8n8.x4.shared.b16 {%0,%1,%2,%3}, [%4];"
        : "=r"(r0), "=r"(r1), "=r"(r2), "=r"(r3) : "r"(addr));
}

__device__ __forceinline__ void cp16(uint32_t sa, const void* g) {
    asm volatile("cp.async.cg.shared.global [%0], [%1], 16;" :: "r"(sa), "l"(g));
}
#define CP_COMMIT() asm volatile("cp.async.commit_group;")
#define CP_WAIT1()  asm volatile("cp.async.wait_group 1;")
#define CP_WAIT0()  asm volatile("cp.async.wait_group 0;")

// ------------------------------------------------- K0: pre-round weights
__global__ __launch_bounds__(256) void round_w_kernel(
    const float* __restrict__ kv_w, const float* __restrict__ proj_w)
{
    int i = blockIdx.x * 256 + threadIdx.x;
    if (i < 2 * C_ * C_) g_wkv[i] = rtf32(kv_w[i]);
    if (i < C_ * C_)     g_wpj[i] = rtf32(proj_w[i]);
}

// ---------------------------------------------------------------- K1: LN+GELU
__global__ __launch_bounds__(256) void ln_gelu_kernel(
    const float* __restrict__ x,
    const float* __restrict__ lw,
    const float* __restrict__ lb)
{
    int t = (blockIdx.x * 256 + threadIdx.x) >> 5;
    int lane = threadIdx.x & 31;
    const float4* xr = (const float4*)(x + (size_t)t * C_);
    float4* outr = (float4*)(g_xg + (size_t)t * C_);

    float4 a = xr[lane], bq = xr[lane + 32], cq = xr[lane + 64];
    float s = a.x + a.y + a.z + a.w + bq.x + bq.y + bq.z + bq.w
            + cq.x + cq.y + cq.z + cq.w;
    float q = a.x*a.x + a.y*a.y + a.z*a.z + a.w*a.w
            + bq.x*bq.x + bq.y*bq.y + bq.z*bq.z + bq.w*bq.w
            + cq.x*cq.x + cq.y*cq.y + cq.z*cq.z + cq.w*cq.w;
    #pragma unroll
    for (int o = 16; o > 0; o >>= 1) {
        s += __shfl_xor_sync(0xffffffffu, s, o);
        q += __shfl_xor_sync(0xffffffffu, q, o);
    }
    float mu  = s * (1.0f / C_);
    float var = q * (1.0f / C_) - mu * mu;
    float rs  = rsqrtf(var + 1e-6f);

    const float4* lw4 = (const float4*)lw;
    const float4* lb4 = (const float4*)lb;
    #pragma unroll
    for (int j = 0; j < 3; j++) {
        float4 v = (j == 0) ? a : ((j == 1) ? bq : cq);
        float4 w = lw4[lane + j * 32];
        float4 bb = lb4[lane + j * 32];
        float4 o;
        float y;
        y = (v.x - mu) * rs * w.x + bb.x;
        o.x = rtf32(0.5f * y * (1.0f + erff(y * 0.70710678118654752f)));
        y = (v.y - mu) * rs * w.y + bb.y;
        o.y = rtf32(0.5f * y * (1.0f + erff(y * 0.70710678118654752f)));
        y = (v.z - mu) * rs * w.z + bb.z;
        o.z = rtf32(0.5f * y * (1.0f + erff(y * 0.70710678118654752f)));
        y = (v.w - mu) * rs * w.w + bb.w;
        o.w = rtf32(0.5f * y * (1.0f + erff(y * 0.70710678118654752f)));
        outr[lane + j * 32] = o;
    }
}

// ============= shared 3-stage pipelined tf32 GEMM core (128x128 CTA) =========
// A,B tiles [row][k], tf32-exact values -> raw bit feed, scalar LDS frags
// (R8 known-good core: kv ~400us, proj ~23.5us).
#define GSTRIDE 20
#define GSTAGEW (128 * GSTRIDE)
#define GBOFF   (3 * GSTAGEW)
#define GSMEMB  (6 * GSTAGEW * 4)

__device__ __forceinline__ void gemm_cp_chunk(
    float* sm, int stage, int tid, const float* Abase, const float* Bbase, int c)
{
    float* as = sm + stage * GSTAGEW;
    float* bs = sm + GBOFF + stage * GSTAGEW;
    #pragma unroll
    for (int j = 0; j < 2; j++) {
        int cidx = tid + j * 256;
        int row = cidx >> 2, kq = cidx & 3;
        cp16((uint32_t)__cvta_generic_to_shared(as + row * GSTRIDE + kq * 4),
             Abase + (size_t)row * C_ + c * 16 + kq * 4);
        cp16((uint32_t)__cvta_generic_to_shared(bs + row * GSTRIDE + kq * 4),
             Bbase + (size_t)row * C_ + c * 16 + kq * 4);
    }
    CP_COMMIT();
}

__device__ __forceinline__ void gemm_mainloop(
    float* sm, int tid, const float* Abase, const float* Bbase,
    float acc[4][4][4], int wm, int wn, int fr, int fk)
{
    gemm_cp_chunk(sm, 0, tid, Abase, Bbase, 0);
    gemm_cp_chunk(sm, 1, tid, Abase, Bbase, 1);

    for (int c = 0; c < 24; c++) {
        if (c >= 22) { CP_WAIT0(); } else { CP_WAIT1(); }
        __syncthreads();
        const unsigned* As = (const unsigned*)(sm + (c % 3) * GSTAGEW);
        const unsigned* Bs = (const unsigned*)(sm + GBOFF + (c % 3) * GSTAGEW);

        #pragma unroll
        for (int kp = 0; kp < 16; kp += 8) {
            unsigned af[4][4];
            #pragma unroll
            for (int mt = 0; mt < 4; mt++) {
                int rb = wm * 64 + mt * 16 + fr;
                af[mt][0] = As[rb * GSTRIDE + kp + fk];
                af[mt][1] = As[(rb + 8) * GSTRIDE + kp + fk];
                af[mt][2] = As[rb * GSTRIDE + kp + fk + 4];
                af[mt][3] = As[(rb + 8) * GSTRIDE + kp + fk + 4];
            }
            unsigned bf[4][2];
            #pragma unroll
            for (int nt = 0; nt < 4; nt++) {
                int cb = wn * 32 + nt * 8 + fr;
                bf[nt][0] = Bs[cb * GSTRIDE + kp + fk];
                bf[nt][1] = Bs[cb * GSTRIDE + kp + fk + 4];
            }
            #pragma unroll
            for (int mt = 0; mt < 4; mt++)
                #pragma unroll
                for (int nt = 0; nt < 4; nt++)
                    mma_tf32(acc[mt][nt], af[mt], bf[nt]);
        }

        if (c + 2 < 24)
            gemm_cp_chunk(sm, (c + 2) % 3, tid, Abase, Bbase, c + 2);
    }
}

// --------------------------------------------------------- K2: kv GEMM (tf32)
__global__ void __launch_bounds__(256, 2) mma_kv_kernel()
{
    extern __shared__ float sm[];
    int n0 = blockIdx.x * 128;
    int m0 = blockIdx.y * 128;
    int tid = threadIdx.x;
    int wid = tid >> 5, lane = tid & 31;
    int wm = wid >> 2, wn = wid & 3;
    int fr = lane >> 2, fk = lane & 3;

    float acc[4][4][4];
    #pragma unroll
    for (int i = 0; i < 4; i++)
        #pragma unroll
        for (int j = 0; j < 4; j++)
            #pragma unroll
            for (int r = 0; r < 4; r++) acc[i][j][r] = 0.0f;

    gemm_mainloop(sm, tid, g_xg + (size_t)m0 * C_, g_wkv + (size_t)n0 * C_,
                  acc, wm, wn, fr, fk);

    #pragma unroll
    for (int mt = 0; mt < 4; mt++) {
        #pragma unroll
        for (int half = 0; half < 2; half++) {
            int r  = m0 + wm * 64 + mt * 16 + fr + half * 8;
            int bb = r / N_;
            int nn = r - bb * N_;
            #pragma unroll
            for (int nt = 0; nt < 4; nt++) {
                int c  = n0 + wn * 32 + nt * 8 + fk * 2;
                int cc = (c >= C_) ? (c - C_) : c;
                int h  = cc / DH_;
                int d  = cc - h * DH_;
                float* dst = (c >= C_) ? g_v : g_k;
                float2 val;
                val.x = rtf32(acc[mt][nt][half * 2 + 0]);
                val.y = rtf32(acc[mt][nt][half * 2 + 1]);
                *(float2*)(dst + (((size_t)bb * H_ + h) * N_ + nn) * DH_ + d) = val;
            }
        }
    }
}

// -------------------------------------------------------------- K4: proj GEMM
__global__ void __launch_bounds__(256, 2) mma_proj_kernel(
    const float* __restrict__ bias,
    float* __restrict__ out)
{
    extern __shared__ float sm[];
    int n0 = blockIdx.x * 128;
    int m0 = blockIdx.y * 128;
    int tid = threadIdx.x;
    int wid = tid >> 5, lane = tid & 31;
    int wm = wid >> 2, wn = wid & 3;
    int fr = lane >> 2, fk = lane & 3;

    float acc[4][4][4];
    #pragma unroll
    for (int i = 0; i < 4; i++)
        #pragma unroll
        for (int j = 0; j < 4; j++)
            #pragma unroll
            for (int r = 0; r < 4; r++) acc[i][j][r] = 0.0f;

    gemm_mainloop(sm, tid, g_ao + (size_t)m0 * C_, g_wpj + (size_t)n0 * C_,
                  acc, wm, wn, fr, fk);

    #pragma unroll
    for (int mt = 0; mt < 4; mt++) {
        #pragma unroll
        for (int half = 0; half < 2; half++) {
            int r = m0 + wm * 64 + mt * 16 + fr + half * 8;
            #pragma unroll
            for (int nt = 0; nt < 4; nt++) {
                int c = n0 + wn * 32 + nt * 8 + fk * 2;
                float2 val;
                val.x = acc[mt][nt][half * 2 + 0] + bias[c];
                val.y = acc[mt][nt][half * 2 + 1] + bias[c + 1];
                *(float2*)(out + (size_t)r * C_ + c) = val;
            }
        }
    }
}

// ------------------------------------------------------------- K3: MMA attn
// 13 warps (416 thr), one 16-row M-tile per warp, 2 CTAs/SM (R11 known-good).
#define AT_THREADS 416
#define QROWS 208
#define QS_STRIDE 52
#define KS_OFF 10816
#define KS_STRIDE 52
#define KS_BUFW 3328
#define VS_OFF 17472
#define VS_STRIDE 56
#define VS_BUFW 3584
#define PS_OFF 24640
#define PS_STRIDE 12
#define AT_SMEMW 27712

__global__ void __launch_bounds__(AT_THREADS, 2) attn_mma_kernel(const float* __restrict__ qp)
{
    extern __shared__ uint32_t smv[];
    int tid = threadIdx.x;
    int bh = blockIdx.x;
    int b = bh >> 3, h = bh & 7;
    int wid = tid >> 5, lane = tid & 31;
    int fr = lane >> 2, fk = lane & 3;
    int g = lane >> 3, lr = lane & 7;

    const float* kbase = g_k + (size_t)bh * N_ * DH_;
    const float* vbase = g_v + (size_t)bh * N_ * DH_;

    for (int idx = tid; idx < QROWS * 48; idx += AT_THREADS) {
        int m = idx / 48, d = idx - m * 48;
        float v = (m < M_) ? qp[((size_t)m * H_ + h) * DH_ + d] : 0.0f;
        smv[m * QS_STRIDE + d] = f2tf32(v);
    }

    for (int cidx = tid; cidx < 768; cidx += AT_THREADS) {
        int r = cidx / 12, cc = cidx - r * 12;
        cp16((uint32_t)__cvta_generic_to_shared(smv + KS_OFF + r * KS_STRIDE + cc * 4),
             (const float4*)kbase + cidx);
        cp16((uint32_t)__cvta_generic_to_shared(smv + VS_OFF + r * VS_STRIDE + cc * 4),
             (const float4*)vbase + cidx);
    }
    CP_COMMIT();
    __syncthreads();

    unsigned qf[6][4];
    {
        int r0 = wid * 16 + fr;
        #pragma unroll
        for (int kt = 0; kt < 6; kt++) {
            qf[kt][0] = smv[r0 * QS_STRIDE + kt * 8 + fk];
            qf[kt][1] = smv[(r0 + 8) * QS_STRIDE + kt * 8 + fk];
            qf[kt][2] = smv[r0 * QS_STRIDE + kt * 8 + fk + 4];
            qf[kt][3] = smv[(r0 + 8) * QS_STRIDE + kt * 8 + fk + 4];
        }
    }

    float oacc[6][4];
    #pragma unroll
    for (int j = 0; j < 6; j++)
        #pragma unroll
        for (int r = 0; r < 4; r++) oacc[j][r] = 0.0f;
    float lsum[2] = {0.f, 0.f};

    uint32_t ps_base = PS_OFF + wid * 16 * PS_STRIDE;
    uint32_t sm_sh = (uint32_t)__cvta_generic_to_shared(smv);
    // per-thread ldmatrix column offset for K-frags (row = key, col = d-words)
    uint32_t kcol_off = (uint32_t)(((g >> 1) * 8 + (g & 1) * 4) * 4);

    for (int c = 0; c < 49; c++) {
        int buf = c & 1;
        if (c + 1 < 49) {
            int nb = buf ^ 1;
            const float4* ks = (const float4*)(kbase + (size_t)(c + 1) * 64 * DH_);
            const float4* vs = (const float4*)(vbase + (size_t)(c + 1) * 64 * DH_);
            for (int cidx = tid; cidx < 768; cidx += AT_THREADS) {
                int r = cidx / 12, cc2 = cidx - r * 12;
                cp16((uint32_t)__cvta_generic_to_shared(
                         smv + KS_OFF + nb * KS_BUFW + r * KS_STRIDE + cc2 * 4),
                     ks + cidx);
                cp16((uint32_t)__cvta_generic_to_shared(
                         smv + VS_OFF + nb * VS_BUFW + r * VS_STRIDE + cc2 * 4),
                     vs + cidx);
            }
            CP_COMMIT();
            CP_WAIT1();
        } else {
            CP_WAIT0();
        }
        __syncthreads();

        uint32_t kb_sh = sm_sh + (uint32_t)((KS_OFF + buf * KS_BUFW) * 4);
        const uint32_t* vb = smv + VS_OFF + buf * VS_BUFW;

        for (int sub = 0; sub < 8; sub++) {
            // ---- QK: K-frags via ldmatrix (rows = 8 keys of sub) ----
            float s0[4] = {0.f, 0.f, 0.f, 0.f};
            uint32_t krow = kb_sh + (uint32_t)(((sub * 8 + lr) * KS_STRIDE) * 4) + kcol_off;
            #pragma unroll
            for (int jp = 0; jp < 3; jp++) {
                unsigned bk0[2], bk1[2];
                ldsm_x4(bk0[0], bk0[1], bk1[0], bk1[1],
                        krow + (uint32_t)(jp * 64));   // 16 words per kt-pair
                mma_tf32(s0, qf[2 * jp], bk0);
                mma_tf32(s0, qf[2 * jp + 1], bk1);
            }
            // ---- exp + P store + lsum ----
            {
                unsigned c0 = f2tf32(__expf(s0[0]));
                unsigned c1 = f2tf32(__expf(s0[1]));
                unsigned c2 = f2tf32(__expf(s0[2]));
                unsigned c3 = f2tf32(__expf(s0[3]));
                lsum[0] += __uint_as_float(c0) + __uint_as_float(c1);
                lsum[1] += __uint_as_float(c2) + __uint_as_float(c3);
                uint32_t a0 = ps_base + fr * PS_STRIDE + 2 * fk;
                smv[a0] = c0; smv[a0 + 1] = c1;
                uint32_t a1 = ps_base + (fr + 8) * PS_STRIDE + 2 * fk;
                smv[a1] = c2; smv[a1 + 1] = c3;
            }
            __syncwarp();
            unsigned pa[4];
            pa[0] = smv[ps_base + fr * PS_STRIDE + fk];
            pa[1] = smv[ps_base + (fr + 8) * PS_STRIDE + fk];
            pa[2] = smv[ps_base + fr * PS_STRIDE + fk + 4];
            pa[3] = smv[ps_base + (fr + 8) * PS_STRIDE + fk + 4];
            __syncwarp();
            // ---- PV (V scalar loads; transposed access, no ldmatrix) ----
            #pragma unroll
            for (int nt = 0; nt < 6; nt++) {
                unsigned vv[2];
                vv[0] = vb[(sub * 8 + fk) * VS_STRIDE + nt * 8 + fr];
                vv[1] = vb[(sub * 8 + fk + 4) * VS_STRIDE + nt * 8 + fr];
                mma_tf32(oacc[nt], pa, vv);
            }
        }
        __syncthreads();
    }

    // ---- epilogue ----
    #pragma unroll
    for (int hh = 0; hh < 2; hh++) {
        float l = lsum[hh];
        l += __shfl_xor_sync(0xffffffffu, l, 1);
        l += __shfl_xor_sync(0xffffffffu, l, 2);
        float inv = 1.0f / l;
        int m = wid * 16 + fr + hh * 8;
        if (m < M_) {
            float* orow = g_ao + ((size_t)b * M_ + m) * C_ + h * DH_;
            #pragma unroll
            for (int nt = 0; nt < 6; nt++) {
                float2 val;
                val.x = rtf32(oacc[nt][hh * 2 + 0] * inv);
                val.y = rtf32(oacc[nt][hh * 2 + 1] * inv);
                *(float2*)(orow + nt * 8 + 2 * fk) = val;
            }
        }
    }
}

// ----------------------------------------------------------------- launcher
extern "C" void kernel_launch(void* const* d_in, const int* in_sizes, int n_in,
                              void* d_out, int out_size)
{
    const float* x      = (const float*)d_in[0];
    const float* qp     = (const float*)d_in[1];
    const float* kv_w   = (const float*)d_in[2];
    const float* proj_w = (const float*)d_in[3];
    const float* proj_b = (const float*)d_in[4];
    const float* ln_w   = (const float*)d_in[5];
    const float* ln_b   = (const float*)d_in[6];
    float* out = (float*)d_out;

    cudaFuncSetAttribute(attn_mma_kernel,
                         cudaFuncAttributeMaxDynamicSharedMemorySize, AT_SMEMW * 4);
    cudaFuncSetAttribute(mma_kv_kernel,
                         cudaFuncAttributeMaxDynamicSharedMemorySize, GSMEMB);
    cudaFuncSetAttribute(mma_proj_kernel,
                         cudaFuncAttributeMaxDynamicSharedMemorySize, GSMEMB);

    round_w_kernel<<<(2 * C_ * C_ + 255) / 256, 256>>>(kv_w, proj_w);

    ln_gelu_kernel<<<T_ / 8, 256>>>(x, ln_w, ln_b);

    dim3 g2(6, 784);
    mma_kv_kernel<<<g2, 256, GSMEMB>>>();

    attn_mma_kernel<<<B_ * H_, AT_THREADS, AT_SMEMW * 4>>>(qp);

    dim3 g4(3, 49);
    mma_proj_kernel<<<g4, 256, GSMEMB>>>(proj_b, out);
}

// round 13
// speedup vs baseline: 1.1173x; 1.0133x over previous
#include <cuda_runtime.h>
#include <math.h>
#include <stdint.h>

// Problem dims
#define B_   32
#define N_   3136
#define C_   384
#define H_   8
#define DH_  48
#define M_   196
#define T_   (B_ * N_)          // 100352 tokens

// ---------------- scratch (static device globals; no runtime allocation) ---
__device__ float g_xg[T_ * C_];              // gelu(ln(x)), tf32-valued
__device__ float g_k [B_ * H_ * N_ * DH_];   // k [b,h,n,d], tf32-valued
__device__ float g_v [B_ * H_ * DH_ * N_];   // v [b,h,d,n] (TRANSPOSED), tf32-valued
__device__ float g_ao[B_ * M_ * C_];         // attn out [b,m,c], tf32-valued
__device__ float g_wkv[2 * C_ * C_];         // kv_w pre-rounded to tf32
__device__ float g_wpj[C_ * C_];             // proj_w pre-rounded to tf32

// ------------------------------------------------------ tf32 helpers
__device__ __forceinline__ unsigned f2tf32(float f) {
    unsigned r;
    asm("cvt.rna.tf32.f32 %0, %1;" : "=r"(r) : "f"(f));
    return r;
}
__device__ __forceinline__ float rtf32(float f) { return __uint_as_float(f2tf32(f)); }

__device__ __forceinline__ void mma_tf32(float* c, const unsigned* a, const unsigned* b) {
    asm volatile(
        "mma.sync.aligned.m16n8k8.row.col.f32.tf32.tf32.f32 "
        "{%0,%1,%2,%3}, {%4,%5,%6,%7}, {%8,%9}, {%0,%1,%2,%3};"
        : "+f"(c[0]), "+f"(c[1]), "+f"(c[2]), "+f"(c[3])
        : "r"(a[0]), "r"(a[1]), "r"(a[2]), "r"(a[3]),
          "r"(b[0]), "r"(b[1]));
}

// ldmatrix x4 on 32-bit (tf32) data viewed as b16 pairs:
// per 8x4(32-bit) tile, thread t gets element (row t/4, col t%4).
__device__ __forceinline__ void ldsm_x4(unsigned &r0, unsigned &r1,
                                        unsigned &r2, unsigned &r3, uint32_t addr) {
    asm volatile("ldmatrix.sync.aligned.m8n8.x4.shared.b16 {%0,%1,%2,%3}, [%4];"
        : "=r"(r0), "=r"(r1), "=r"(r2), "=r"(r3) : "r"(addr));
}

__device__ __forceinline__ void cp16(uint32_t sa, const void* g) {
    asm volatile("cp.async.cg.shared.global [%0], [%1], 16;" :: "r"(sa), "l"(g));
}
#define CP_COMMIT() asm volatile("cp.async.commit_group;")
#define CP_WAIT1()  asm volatile("cp.async.wait_group 1;")
#define CP_WAIT0()  asm volatile("cp.async.wait_group 0;")

// ------------------------------------------------- K0: pre-round weights
__global__ __launch_bounds__(256) void round_w_kernel(
    const float* __restrict__ kv_w, const float* __restrict__ proj_w)
{
    int i = blockIdx.x * 256 + threadIdx.x;
    if (i < 2 * C_ * C_) g_wkv[i] = rtf32(kv_w[i]);
    if (i < C_ * C_)     g_wpj[i] = rtf32(proj_w[i]);
}

// ---------------------------------------------------------------- K1: LN+GELU
__global__ __launch_bounds__(256) void ln_gelu_kernel(
    const float* __restrict__ x,
    const float* __restrict__ lw,
    const float* __restrict__ lb)
{
    int t = (blockIdx.x * 256 + threadIdx.x) >> 5;
    int lane = threadIdx.x & 31;
    const float4* xr = (const float4*)(x + (size_t)t * C_);
    float4* outr = (float4*)(g_xg + (size_t)t * C_);

    float4 a = xr[lane], bq = xr[lane + 32], cq = xr[lane + 64];
    float s = a.x + a.y + a.z + a.w + bq.x + bq.y + bq.z + bq.w
            + cq.x + cq.y + cq.z + cq.w;
    float q = a.x*a.x + a.y*a.y + a.z*a.z + a.w*a.w
            + bq.x*bq.x + bq.y*bq.y + bq.z*bq.z + bq.w*bq.w
            + cq.x*cq.x + cq.y*cq.y + cq.z*cq.z + cq.w*cq.w;
    #pragma unroll
    for (int o = 16; o > 0; o >>= 1) {
        s += __shfl_xor_sync(0xffffffffu, s, o);
        q += __shfl_xor_sync(0xffffffffu, q, o);
    }
    float mu  = s * (1.0f / C_);
    float var = q * (1.0f / C_) - mu * mu;
    float rs  = rsqrtf(var + 1e-6f);

    const float4* lw4 = (const float4*)lw;
    const float4* lb4 = (const float4*)lb;
    #pragma unroll
    for (int j = 0; j < 3; j++) {
        float4 v = (j == 0) ? a : ((j == 1) ? bq : cq);
        float4 w = lw4[lane + j * 32];
        float4 bb = lb4[lane + j * 32];
        float4 o;
        float y;
        y = (v.x - mu) * rs * w.x + bb.x;
        o.x = rtf32(0.5f * y * (1.0f + erff(y * 0.70710678118654752f)));
        y = (v.y - mu) * rs * w.y + bb.y;
        o.y = rtf32(0.5f * y * (1.0f + erff(y * 0.70710678118654752f)));
        y = (v.z - mu) * rs * w.z + bb.z;
        o.z = rtf32(0.5f * y * (1.0f + erff(y * 0.70710678118654752f)));
        y = (v.w - mu) * rs * w.w + bb.w;
        o.w = rtf32(0.5f * y * (1.0f + erff(y * 0.70710678118654752f)));
        outr[lane + j * 32] = o;
    }
}

// ============= shared 3-stage pipelined tf32 GEMM core (128x128 CTA) =========
// A,B tiles [row][k], tf32-exact values -> raw bit feed, scalar LDS frags
// (R8/R12 known-good core: kv ~400us, proj ~23.5us).
#define GSTRIDE 20
#define GSTAGEW (128 * GSTRIDE)
#define GBOFF   (3 * GSTAGEW)
#define GSMEMB  (6 * GSTAGEW * 4)

__device__ __forceinline__ void gemm_cp_chunk(
    float* sm, int stage, int tid, const float* Abase, const float* Bbase, int c)
{
    float* as = sm + stage * GSTAGEW;
    float* bs = sm + GBOFF + stage * GSTAGEW;
    #pragma unroll
    for (int j = 0; j < 2; j++) {
        int cidx = tid + j * 256;
        int row = cidx >> 2, kq = cidx & 3;
        cp16((uint32_t)__cvta_generic_to_shared(as + row * GSTRIDE + kq * 4),
             Abase + (size_t)row * C_ + c * 16 + kq * 4);
        cp16((uint32_t)__cvta_generic_to_shared(bs + row * GSTRIDE + kq * 4),
             Bbase + (size_t)row * C_ + c * 16 + kq * 4);
    }
    CP_COMMIT();
}

__device__ __forceinline__ void gemm_mainloop(
    float* sm, int tid, const float* Abase, const float* Bbase,
    float acc[4][4][4], int wm, int wn, int fr, int fk)
{
    gemm_cp_chunk(sm, 0, tid, Abase, Bbase, 0);
    gemm_cp_chunk(sm, 1, tid, Abase, Bbase, 1);

    for (int c = 0; c < 24; c++) {
        if (c >= 22) { CP_WAIT0(); } else { CP_WAIT1(); }
        __syncthreads();
        const unsigned* As = (const unsigned*)(sm + (c % 3) * GSTAGEW);
        const unsigned* Bs = (const unsigned*)(sm + GBOFF + (c % 3) * GSTAGEW);

        #pragma unroll
        for (int kp = 0; kp < 16; kp += 8) {
            unsigned af[4][4];
            #pragma unroll
            for (int mt = 0; mt < 4; mt++) {
                int rb = wm * 64 + mt * 16 + fr;
                af[mt][0] = As[rb * GSTRIDE + kp + fk];
                af[mt][1] = As[(rb + 8) * GSTRIDE + kp + fk];
                af[mt][2] = As[rb * GSTRIDE + kp + fk + 4];
                af[mt][3] = As[(rb + 8) * GSTRIDE + kp + fk + 4];
            }
            unsigned bf[4][2];
            #pragma unroll
            for (int nt = 0; nt < 4; nt++) {
                int cb = wn * 32 + nt * 8 + fr;
                bf[nt][0] = Bs[cb * GSTRIDE + kp + fk];
                bf[nt][1] = Bs[cb * GSTRIDE + kp + fk + 4];
            }
            #pragma unroll
            for (int mt = 0; mt < 4; mt++)
                #pragma unroll
                for (int nt = 0; nt < 4; nt++)
                    mma_tf32(acc[mt][nt], af[mt], bf[nt]);
        }

        if (c + 2 < 24)
            gemm_cp_chunk(sm, (c + 2) % 3, tid, Abase, Bbase, c + 2);
    }
}

// --------------------------------------------------------- K2: kv GEMM (tf32)
// k epilogue -> g_k [b,h,n,d]; v epilogue -> g_v [b,h,d,n] (transposed).
__global__ void __launch_bounds__(256, 2) mma_kv_kernel()
{
    extern __shared__ float sm[];
    int n0 = blockIdx.x * 128;
    int m0 = blockIdx.y * 128;
    int tid = threadIdx.x;
    int wid = tid >> 5, lane = tid & 31;
    int wm = wid >> 2, wn = wid & 3;
    int fr = lane >> 2, fk = lane & 3;

    float acc[4][4][4];
    #pragma unroll
    for (int i = 0; i < 4; i++)
        #pragma unroll
        for (int j = 0; j < 4; j++)
            #pragma unroll
            for (int r = 0; r < 4; r++) acc[i][j][r] = 0.0f;

    gemm_mainloop(sm, tid, g_xg + (size_t)m0 * C_, g_wkv + (size_t)n0 * C_,
                  acc, wm, wn, fr, fk);

    #pragma unroll
    for (int mt = 0; mt < 4; mt++) {
        #pragma unroll
        for (int half = 0; half < 2; half++) {
            int r  = m0 + wm * 64 + mt * 16 + fr + half * 8;
            int bb = r / N_;
            int nn = r - bb * N_;
            #pragma unroll
            for (int nt = 0; nt < 4; nt++) {
                int c  = n0 + wn * 32 + nt * 8 + fk * 2;
                float vx = rtf32(acc[mt][nt][half * 2 + 0]);
                float vy = rtf32(acc[mt][nt][half * 2 + 1]);
                if (c < C_) {
                    int h  = c / DH_;
                    int d  = c - h * DH_;
                    float2 val; val.x = vx; val.y = vy;
                    *(float2*)(g_k + (((size_t)bb * H_ + h) * N_ + nn) * DH_ + d) = val;
                } else {
                    int cc = c - C_;
                    int h  = cc / DH_;
                    int d  = cc - h * DH_;
                    float* dst = g_v + (((size_t)bb * H_ + h) * DH_ + d) * N_ + nn;
                    dst[0]  = vx;      // d
                    dst[N_] = vy;      // d+1
                }
            }
        }
    }
}

// -------------------------------------------------------------- K4: proj GEMM
__global__ void __launch_bounds__(256, 2) mma_proj_kernel(
    const float* __restrict__ bias,
    float* __restrict__ out)
{
    extern __shared__ float sm[];
    int n0 = blockIdx.x * 128;
    int m0 = blockIdx.y * 128;
    int tid = threadIdx.x;
    int wid = tid >> 5, lane = tid & 31;
    int wm = wid >> 2, wn = wid & 3;
    int fr = lane >> 2, fk = lane & 3;

    float acc[4][4][4];
    #pragma unroll
    for (int i = 0; i < 4; i++)
        #pragma unroll
        for (int j = 0; j < 4; j++)
            #pragma unroll
            for (int r = 0; r < 4; r++) acc[i][j][r] = 0.0f;

    gemm_mainloop(sm, tid, g_ao + (size_t)m0 * C_, g_wpj + (size_t)n0 * C_,
                  acc, wm, wn, fr, fk);

    #pragma unroll
    for (int mt = 0; mt < 4; mt++) {
        #pragma unroll
        for (int half = 0; half < 2; half++) {
            int r = m0 + wm * 64 + mt * 16 + fr + half * 8;
            #pragma unroll
            for (int nt = 0; nt < 4; nt++) {
                int c = n0 + wn * 32 + nt * 8 + fk * 2;
                float2 val;
                val.x = acc[mt][nt][half * 2 + 0] + bias[c];
                val.y = acc[mt][nt][half * 2 + 1] + bias[c + 1];
                *(float2*)(out + (size_t)r * C_ + c) = val;
            }
        }
    }
}

// ------------------------------------------------------------- K3: MMA attn
// 13 warps (416 thr), one 16-row M-tile per warp, 2 CTAs/SM.
// K smem [key][d] stride 52 (ldmatrix); V smem [d][key] stride 68 (ldmatrix,
// conflict-free: 17r mod 8 distinct). P bounce via smem (stride 12).
#define AT_THREADS 416
#define QROWS 208
#define QS_STRIDE 52
#define KS_OFF 10816
#define KS_STRIDE 52
#define KS_BUFW 3328            // 64*52
#define VS_OFF 17472
#define VS_STRIDE 68            // 64 keys + 4 pad
#define VS_BUFW 3264            // 48*68
#define PS_OFF 24000
#define PS_STRIDE 12
#define AT_SMEMW 26496          // words (105984 B)

__global__ void __launch_bounds__(AT_THREADS, 2) attn_mma_kernel(const float* __restrict__ qp)
{
    extern __shared__ uint32_t smv[];
    int tid = threadIdx.x;
    int bh = blockIdx.x;
    int b = bh >> 3, h = bh & 7;
    int wid = tid >> 5, lane = tid & 31;
    int fr = lane >> 2, fk = lane & 3;
    int g = lane >> 3, lr = lane & 7;

    const float* kbase = g_k + (size_t)bh * N_ * DH_;
    const float* vbase = g_v + (size_t)bh * DH_ * N_;   // [d][n]

    for (int idx = tid; idx < QROWS * 48; idx += AT_THREADS) {
        int m = idx / 48, d = idx - m * 48;
        float v = (m < M_) ? qp[((size_t)m * H_ + h) * DH_ + d] : 0.0f;
        smv[m * QS_STRIDE + d] = f2tf32(v);
    }

    // prologue: chunk 0 -> buf 0
    for (int cidx = tid; cidx < 768; cidx += AT_THREADS) {
        int r = cidx / 12, cc = cidx - r * 12;   // K: [key r][d-unit cc]
        cp16((uint32_t)__cvta_generic_to_shared(smv + KS_OFF + r * KS_STRIDE + cc * 4),
             (const float4*)kbase + cidx);
    }
    for (int cidx = tid; cidx < 768; cidx += AT_THREADS) {
        int d = cidx >> 4, u = cidx & 15;        // V: [d][key-unit u]
        cp16((uint32_t)__cvta_generic_to_shared(smv + VS_OFF + d * VS_STRIDE + u * 4),
             vbase + (size_t)d * N_ + u * 4);
    }
    CP_COMMIT();
    __syncthreads();

    unsigned qf[6][4];
    {
        int r0 = wid * 16 + fr;
        #pragma unroll
        for (int kt = 0; kt < 6; kt++) {
            qf[kt][0] = smv[r0 * QS_STRIDE + kt * 8 + fk];
            qf[kt][1] = smv[(r0 + 8) * QS_STRIDE + kt * 8 + fk];
            qf[kt][2] = smv[r0 * QS_STRIDE + kt * 8 + fk + 4];
            qf[kt][3] = smv[(r0 + 8) * QS_STRIDE + kt * 8 + fk + 4];
        }
    }

    float oacc[6][4];
    #pragma unroll
    for (int j = 0; j < 6; j++)
        #pragma unroll
        for (int r = 0; r < 4; r++) oacc[j][r] = 0.0f;
    float lsum[2] = {0.f, 0.f};

    uint32_t ps_base = PS_OFF + wid * 16 * PS_STRIDE;
    uint32_t sm_sh = (uint32_t)__cvta_generic_to_shared(smv);
    // K ldmatrix per-thread column offset (row = key, col = d-words)
    uint32_t kcol_off = (uint32_t)(((g >> 1) * 8 + (g & 1) * 4) * 4);
    // V ldmatrix per-thread row offset: matrix m = lane>>3, row r = lane&7
    // matrix m -> (nt = 2p + (m>>1), key-half = m&1)
    int vm = lane >> 3, vr = lane & 7;
    uint32_t vrow_off = (uint32_t)(((((vm >> 1) << 3) + vr) * VS_STRIDE + (vm & 1) * 4) * 4);

    for (int c = 0; c < 49; c++) {
        int buf = c & 1;
        if (c + 1 < 49) {
            int nb = buf ^ 1;
            const float4* ks = (const float4*)(kbase + (size_t)(c + 1) * 64 * DH_);
            const float* vsb = vbase + (c + 1) * 64;
            for (int cidx = tid; cidx < 768; cidx += AT_THREADS) {
                int r = cidx / 12, cc2 = cidx - r * 12;
                cp16((uint32_t)__cvta_generic_to_shared(
                         smv + KS_OFF + nb * KS_BUFW + r * KS_STRIDE + cc2 * 4),
                     ks + cidx);
            }
            for (int cidx = tid; cidx < 768; cidx += AT_THREADS) {
                int d = cidx >> 4, u = cidx & 15;
                cp16((uint32_t)__cvta_generic_to_shared(
                         smv + VS_OFF + nb * VS_BUFW + d * VS_STRIDE + u * 4),
                     vsb + (size_t)d * N_ + u * 4);
            }
            CP_COMMIT();
            CP_WAIT1();
        } else {
            CP_WAIT0();
        }
        __syncthreads();

        uint32_t kb_sh = sm_sh + (uint32_t)((KS_OFF + buf * KS_BUFW) * 4);
        uint32_t vb_sh = sm_sh + (uint32_t)((VS_OFF + buf * VS_BUFW) * 4) + vrow_off;

        for (int sub = 0; sub < 8; sub++) {
            // ---- QK: K-frags via ldmatrix (rows = 8 keys of sub) ----
            float s0[4] = {0.f, 0.f, 0.f, 0.f};
            uint32_t krow = kb_sh + (uint32_t)(((sub * 8 + lr) * KS_STRIDE) * 4) + kcol_off;
            #pragma unroll
            for (int jp = 0; jp < 3; jp++) {
                unsigned bk0[2], bk1[2];
                ldsm_x4(bk0[0], bk0[1], bk1[0], bk1[1],
                        krow + (uint32_t)(jp * 64));   // 16 words per kt-pair
                mma_tf32(s0, qf[2 * jp], bk0);
                mma_tf32(s0, qf[2 * jp + 1], bk1);
            }
            // ---- exp + P store + lsum ----
            {
                unsigned c0 = f2tf32(__expf(s0[0]));
                unsigned c1 = f2tf32(__expf(s0[1]));
                unsigned c2 = f2tf32(__expf(s0[2]));
                unsigned c3 = f2tf32(__expf(s0[3]));
                lsum[0] += __uint_as_float(c0) + __uint_as_float(c1);
                lsum[1] += __uint_as_float(c2) + __uint_as_float(c3);
                uint32_t a0 = ps_base + fr * PS_STRIDE + 2 * fk;
                smv[a0] = c0; smv[a0 + 1] = c1;
                uint32_t a1 = ps_base + (fr + 8) * PS_STRIDE + 2 * fk;
                smv[a1] = c2; smv[a1 + 1] = c3;
            }
            __syncwarp();
            unsigned pa[4];
            pa[0] = smv[ps_base + fr * PS_STRIDE + fk];
            pa[1] = smv[ps_base + (fr + 8) * PS_STRIDE + fk];
            pa[2] = smv[ps_base + fr * PS_STRIDE + fk + 4];
            pa[3] = smv[ps_base + (fr + 8) * PS_STRIDE + fk + 4];
            __syncwarp();
            // ---- PV: V-frags via ldmatrix on transposed V [d][key] ----
            uint32_t vaddr = vb_sh + (uint32_t)(sub * 32);
            #pragma unroll
            for (int p = 0; p < 3; p++) {
                unsigned v0[2], v1[2];
                ldsm_x4(v0[0], v0[1], v1[0], v1[1],
                        vaddr + (uint32_t)(p * (16 * VS_STRIDE * 4)));
                mma_tf32(oacc[2 * p], pa, v0);
                mma_tf32(oacc[2 * p + 1], pa, v1);
            }
        }
        __syncthreads();
    }

    // ---- epilogue ----
    #pragma unroll
    for (int hh = 0; hh < 2; hh++) {
        float l = lsum[hh];
        l += __shfl_xor_sync(0xffffffffu, l, 1);
        l += __shfl_xor_sync(0xffffffffu, l, 2);
        float inv = 1.0f / l;
        int m = wid * 16 + fr + hh * 8;
        if (m < M_) {
            float* orow = g_ao + ((size_t)b * M_ + m) * C_ + h * DH_;
            #pragma unroll
            for (int nt = 0; nt < 6; nt++) {
                float2 val;
                val.x = rtf32(oacc[nt][hh * 2 + 0] * inv);
                val.y = rtf32(oacc[nt][hh * 2 + 1] * inv);
                *(float2*)(orow + nt * 8 + 2 * fk) = val;
            }
        }
    }
}

// ----------------------------------------------------------------- launcher
extern "C" void kernel_launch(void* const* d_in, const int* in_sizes, int n_in,
                              void* d_out, int out_size)
{
    const float* x      = (const float*)d_in[0];
    const float* qp     = (const float*)d_in[1];
    const float* kv_w   = (const float*)d_in[2];
    const float* proj_w = (const float*)d_in[3];
    const float* proj_b = (const float*)d_in[4];
    const float* ln_w   = (const float*)d_in[5];
    const float* ln_b   = (const float*)d_in[6];
    float* out = (float*)d_out;

    cudaFuncSetAttribute(attn_mma_kernel,
                         cudaFuncAttributeMaxDynamicSharedMemorySize, AT_SMEMW * 4);
    cudaFuncSetAttribute(mma_kv_kernel,
                         cudaFuncAttributeMaxDynamicSharedMemorySize, GSMEMB);
    cudaFuncSetAttribute(mma_proj_kernel,
                         cudaFuncAttributeMaxDynamicSharedMemorySize, GSMEMB);

    round_w_kernel<<<(2 * C_ * C_ + 255) / 256, 256>>>(kv_w, proj_w);

    ln_gelu_kernel<<<T_ / 8, 256>>>(x, ln_w, ln_b);

    dim3 g2(6, 784);
    mma_kv_kernel<<<g2, 256, GSMEMB>>>();

    attn_mma_kernel<<<B_ * H_, AT_THREADS, AT_SMEMW * 4>>>(qp);

    dim3 g4(3, 49);
    mma_proj_kernel<<<g4, 256, GSMEMB>>>(proj_b, out);
}

// round 14
// speedup vs baseline: 1.1203x; 1.0027x over previous
#include <cuda_runtime.h>
#include <math.h>
#include <stdint.h>

// Problem dims
#define B_   32
#define N_   3136
#define C_   384
#define H_   8
#define DH_  48
#define M_   196
#define T_   (B_ * N_)          // 100352 tokens

// ---------------- scratch (static device globals; no runtime allocation) ---
__device__ float g_xg[T_ * C_];              // gelu(ln(x)), tf32-valued
__device__ float g_k [B_ * H_ * N_ * DH_];   // k [b,h,n,d], tf32-valued
__device__ float g_v [B_ * H_ * DH_ * N_];   // v [b,h,d,n] (TRANSPOSED), tf32-valued
__device__ float g_ao[B_ * M_ * C_];         // attn out [b,m,c], tf32-valued
__device__ float g_wkv[2 * C_ * C_];         // kv_w pre-rounded to tf32
__device__ float g_wpj[C_ * C_];             // proj_w pre-rounded to tf32

// ------------------------------------------------------ tf32 helpers
__device__ __forceinline__ unsigned f2tf32(float f) {
    unsigned r;
    asm("cvt.rna.tf32.f32 %0, %1;" : "=r"(r) : "f"(f));
    return r;
}
__device__ __forceinline__ float rtf32(float f) { return __uint_as_float(f2tf32(f)); }

__device__ __forceinline__ void mma_tf32(float* c, const unsigned* a, const unsigned* b) {
    asm volatile(
        "mma.sync.aligned.m16n8k8.row.col.f32.tf32.tf32.f32 "
        "{%0,%1,%2,%3}, {%4,%5,%6,%7}, {%8,%9}, {%0,%1,%2,%3};"
        : "+f"(c[0]), "+f"(c[1]), "+f"(c[2]), "+f"(c[3])
        : "r"(a[0]), "r"(a[1]), "r"(a[2]), "r"(a[3]),
          "r"(b[0]), "r"(b[1]));
}

// ldmatrix x4 on 32-bit (tf32) data viewed as b16 pairs:
// per 8x4(32-bit) tile, thread t gets element (row t/4, col t%4).
__device__ __forceinline__ void ldsm_x4(unsigned &r0, unsigned &r1,
                                        unsigned &r2, unsigned &r3, uint32_t addr) {
    asm volatile("ldmatrix.sync.aligned.m8n8.x4.shared.b16 {%0,%1,%2,%3}, [%4];"
        : "=r"(r0), "=r"(r1), "=r"(r2), "=r"(r3) : "r"(addr));
}

__device__ __forceinline__ void cp16(uint32_t sa, const void* g) {
    asm volatile("cp.async.cg.shared.global [%0], [%1], 16;" :: "r"(sa), "l"(g));
}
#define CP_COMMIT() asm volatile("cp.async.commit_group;")
#define CP_WAIT1()  asm volatile("cp.async.wait_group 1;")
#define CP_WAIT0()  asm volatile("cp.async.wait_group 0;")

// ------------------------------------------------- K0: pre-round weights
__global__ __launch_bounds__(256) void round_w_kernel(
    const float* __restrict__ kv_w, const float* __restrict__ proj_w)
{
    int i = blockIdx.x * 256 + threadIdx.x;
    if (i < 2 * C_ * C_) g_wkv[i] = rtf32(kv_w[i]);
    if (i < C_ * C_)     g_wpj[i] = rtf32(proj_w[i]);
}

// ---------------------------------------------------------------- K1: LN+GELU
__global__ __launch_bounds__(256) void ln_gelu_kernel(
    const float* __restrict__ x,
    const float* __restrict__ lw,
    const float* __restrict__ lb)
{
    int t = (blockIdx.x * 256 + threadIdx.x) >> 5;
    int lane = threadIdx.x & 31;
    const float4* xr = (const float4*)(x + (size_t)t * C_);
    float4* outr = (float4*)(g_xg + (size_t)t * C_);

    float4 a = xr[lane], bq = xr[lane + 32], cq = xr[lane + 64];
    float s = a.x + a.y + a.z + a.w + bq.x + bq.y + bq.z + bq.w
            + cq.x + cq.y + cq.z + cq.w;
    float q = a.x*a.x + a.y*a.y + a.z*a.z + a.w*a.w
            + bq.x*bq.x + bq.y*bq.y + bq.z*bq.z + bq.w*bq.w
            + cq.x*cq.x + cq.y*cq.y + cq.z*cq.z + cq.w*cq.w;
    #pragma unroll
    for (int o = 16; o > 0; o >>= 1) {
        s += __shfl_xor_sync(0xffffffffu, s, o);
        q += __shfl_xor_sync(0xffffffffu, q, o);
    }
    float mu  = s * (1.0f / C_);
    float var = q * (1.0f / C_) - mu * mu;
    float rs  = rsqrtf(var + 1e-6f);

    const float4* lw4 = (const float4*)lw;
    const float4* lb4 = (const float4*)lb;
    #pragma unroll
    for (int j = 0; j < 3; j++) {
        float4 v = (j == 0) ? a : ((j == 1) ? bq : cq);
        float4 w = lw4[lane + j * 32];
        float4 bb = lb4[lane + j * 32];
        float4 o;
        float y;
        y = (v.x - mu) * rs * w.x + bb.x;
        o.x = rtf32(0.5f * y * (1.0f + erff(y * 0.70710678118654752f)));
        y = (v.y - mu) * rs * w.y + bb.y;
        o.y = rtf32(0.5f * y * (1.0f + erff(y * 0.70710678118654752f)));
        y = (v.z - mu) * rs * w.z + bb.z;
        o.z = rtf32(0.5f * y * (1.0f + erff(y * 0.70710678118654752f)));
        y = (v.w - mu) * rs * w.w + bb.w;
        o.w = rtf32(0.5f * y * (1.0f + erff(y * 0.70710678118654752f)));
        outr[lane + j * 32] = o;
    }
}

// ============= shared 3-stage pipelined tf32 GEMM core (128x128 CTA) =========
// (R8/R12 known-good core: kv ~400us, proj ~23.5us.)
#define GSTRIDE 20
#define GSTAGEW (128 * GSTRIDE)
#define GBOFF   (3 * GSTAGEW)
#define GSMEMB  (6 * GSTAGEW * 4)

__device__ __forceinline__ void gemm_cp_chunk(
    float* sm, int stage, int tid, const float* Abase, const float* Bbase, int c)
{
    float* as = sm + stage * GSTAGEW;
    float* bs = sm + GBOFF + stage * GSTAGEW;
    #pragma unroll
    for (int j = 0; j < 2; j++) {
        int cidx = tid + j * 256;
        int row = cidx >> 2, kq = cidx & 3;
        cp16((uint32_t)__cvta_generic_to_shared(as + row * GSTRIDE + kq * 4),
             Abase + (size_t)row * C_ + c * 16 + kq * 4);
        cp16((uint32_t)__cvta_generic_to_shared(bs + row * GSTRIDE + kq * 4),
             Bbase + (size_t)row * C_ + c * 16 + kq * 4);
    }
    CP_COMMIT();
}

__device__ __forceinline__ void gemm_mainloop(
    float* sm, int tid, const float* Abase, const float* Bbase,
    float acc[4][4][4], int wm, int wn, int fr, int fk)
{
    gemm_cp_chunk(sm, 0, tid, Abase, Bbase, 0);
    gemm_cp_chunk(sm, 1, tid, Abase, Bbase, 1);

    for (int c = 0; c < 24; c++) {
        if (c >= 22) { CP_WAIT0(); } else { CP_WAIT1(); }
        __syncthreads();
        const unsigned* As = (const unsigned*)(sm + (c % 3) * GSTAGEW);
        const unsigned* Bs = (const unsigned*)(sm + GBOFF + (c % 3) * GSTAGEW);

        #pragma unroll
        for (int kp = 0; kp < 16; kp += 8) {
            unsigned af[4][4];
            #pragma unroll
            for (int mt = 0; mt < 4; mt++) {
                int rb = wm * 64 + mt * 16 + fr;
                af[mt][0] = As[rb * GSTRIDE + kp + fk];
                af[mt][1] = As[(rb + 8) * GSTRIDE + kp + fk];
                af[mt][2] = As[rb * GSTRIDE + kp + fk + 4];
                af[mt][3] = As[(rb + 8) * GSTRIDE + kp + fk + 4];
            }
            unsigned bf[4][2];
            #pragma unroll
            for (int nt = 0; nt < 4; nt++) {
                int cb = wn * 32 + nt * 8 + fr;
                bf[nt][0] = Bs[cb * GSTRIDE + kp + fk];
                bf[nt][1] = Bs[cb * GSTRIDE + kp + fk + 4];
            }
            #pragma unroll
            for (int mt = 0; mt < 4; mt++)
                #pragma unroll
                for (int nt = 0; nt < 4; nt++)
                    mma_tf32(acc[mt][nt], af[mt], bf[nt]);
        }

        if (c + 2 < 24)
            gemm_cp_chunk(sm, (c + 2) % 3, tid, Abase, Bbase, c + 2);
    }
}

// --------------------------------------------------------- K2: kv GEMM (tf32)
// k epilogue -> g_k [b,h,n,d]; v epilogue -> g_v [b,h,d,n] (transposed).
__global__ void __launch_bounds__(256, 2) mma_kv_kernel()
{
    extern __shared__ float sm[];
    int n0 = blockIdx.x * 128;
    int m0 = blockIdx.y * 128;
    int tid = threadIdx.x;
    int wid = tid >> 5, lane = tid & 31;
    int wm = wid >> 2, wn = wid & 3;
    int fr = lane >> 2, fk = lane & 3;

    float acc[4][4][4];
    #pragma unroll
    for (int i = 0; i < 4; i++)
        #pragma unroll
        for (int j = 0; j < 4; j++)
            #pragma unroll
            for (int r = 0; r < 4; r++) acc[i][j][r] = 0.0f;

    gemm_mainloop(sm, tid, g_xg + (size_t)m0 * C_, g_wkv + (size_t)n0 * C_,
                  acc, wm, wn, fr, fk);

    #pragma unroll
    for (int mt = 0; mt < 4; mt++) {
        #pragma unroll
        for (int half = 0; half < 2; half++) {
            int r  = m0 + wm * 64 + mt * 16 + fr + half * 8;
            int bb = r / N_;
            int nn = r - bb * N_;
            #pragma unroll
            for (int nt = 0; nt < 4; nt++) {
                int c  = n0 + wn * 32 + nt * 8 + fk * 2;
                float vx = rtf32(acc[mt][nt][half * 2 + 0]);
                float vy = rtf32(acc[mt][nt][half * 2 + 1]);
                if (c < C_) {
                    int h  = c / DH_;
                    int d  = c - h * DH_;
                    float2 val; val.x = vx; val.y = vy;
                    *(float2*)(g_k + (((size_t)bb * H_ + h) * N_ + nn) * DH_ + d) = val;
                } else {
                    int cc = c - C_;
                    int h  = cc / DH_;
                    int d  = cc - h * DH_;
                    float* dst = g_v + (((size_t)bb * H_ + h) * DH_ + d) * N_ + nn;
                    dst[0]  = vx;      // d
                    dst[N_] = vy;      // d+1
                }
            }
        }
    }
}

// -------------------------------------------------------------- K4: proj GEMM
__global__ void __launch_bounds__(256, 2) mma_proj_kernel(
    const float* __restrict__ bias,
    float* __restrict__ out)
{
    extern __shared__ float sm[];
    int n0 = blockIdx.x * 128;
    int m0 = blockIdx.y * 128;
    int tid = threadIdx.x;
    int wid = tid >> 5, lane = tid & 31;
    int wm = wid >> 2, wn = wid & 3;
    int fr = lane >> 2, fk = lane & 3;

    float acc[4][4][4];
    #pragma unroll
    for (int i = 0; i < 4; i++)
        #pragma unroll
        for (int j = 0; j < 4; j++)
            #pragma unroll
            for (int r = 0; r < 4; r++) acc[i][j][r] = 0.0f;

    gemm_mainloop(sm, tid, g_ao + (size_t)m0 * C_, g_wpj + (size_t)n0 * C_,
                  acc, wm, wn, fr, fk);

    #pragma unroll
    for (int mt = 0; mt < 4; mt++) {
        #pragma unroll
        for (int half = 0; half < 2; half++) {
            int r = m0 + wm * 64 + mt * 16 + fr + half * 8;
            #pragma unroll
            for (int nt = 0; nt < 4; nt++) {
                int c = n0 + wn * 32 + nt * 8 + fk * 2;
                float2 val;
                val.x = acc[mt][nt][half * 2 + 0] + bias[c];
                val.y = acc[mt][nt][half * 2 + 1] + bias[c + 1];
                *(float2*)(out + (size_t)r * C_ + c) = val;
            }
        }
    }
}

// ------------------------------------------------------------- K3: MMA attn
// 13 warps (416 thr), one 16-row M-tile per warp, 2 CTAs/SM.
// Triple-buffered K/V ring (Q smem reused), ONE barrier per chunk.
// K smem [key][d] stride 52 (ldmatrix); V smem [d][key] stride 68 (ldmatrix).
// P C->A fragment remap via register shuffles (no smem bounce, no syncwarp).
#define AT_THREADS 416
#define QROWS 208
#define QS_STRIDE 52
#define KS_STRIDE 52
#define KS_BUFW 3328            // 64*52
#define VS_STRIDE 68            // 64 keys + 4 pad
#define VS_BUFW 3264            // 48*68
#define STAGEW  (KS_BUFW + VS_BUFW)   // 6592 words per ring stage
#define AT_SMEMW (3 * STAGEW)         // 19776 words (79104 B)

// fill chunk c (64 keys) into ring stage s
__device__ __forceinline__ void attn_fill(
    uint32_t sm_sh, int tid, const float* kbase, const float* vbase, int c, int s)
{
    uint32_t stb = sm_sh + (uint32_t)(s * STAGEW * 4);
    const float4* ks = (const float4*)(kbase + (size_t)c * 64 * DH_);
    for (int cidx = tid; cidx < 768; cidx += AT_THREADS) {
        int r = cidx / 12, cc = cidx - r * 12;           // K: [key r][d-unit cc]
        cp16(stb + (uint32_t)((r * KS_STRIDE + cc * 4) * 4), ks + cidx);
    }
    const float* vsb = vbase + c * 64;
    for (int cidx = tid; cidx < 768; cidx += AT_THREADS) {
        int d = cidx >> 4, u = cidx & 15;                // V: [d][key-unit u]
        cp16(stb + (uint32_t)((KS_BUFW + d * VS_STRIDE + u * 4) * 4),
             vsb + (size_t)d * N_ + u * 4);
    }
    CP_COMMIT();
}

__global__ void __launch_bounds__(AT_THREADS, 2) attn_mma_kernel(const float* __restrict__ qp)
{
    extern __shared__ uint32_t smv[];
    int tid = threadIdx.x;
    int bh = blockIdx.x;
    int b = bh >> 3, h = bh & 7;
    int wid = tid >> 5, lane = tid & 31;
    int fr = lane >> 2, fk = lane & 3;
    int g = lane >> 3, lr = lane & 7;

    const float* kbase = g_k + (size_t)bh * N_ * DH_;
    const float* vbase = g_v + (size_t)bh * DH_ * N_;   // [d][n]

    // ---- Q -> smem (ring area, temporary), frags -> regs ----
    for (int idx = tid; idx < QROWS * 48; idx += AT_THREADS) {
        int m = idx / 48, d = idx - m * 48;
        float v = (m < M_) ? qp[((size_t)m * H_ + h) * DH_ + d] : 0.0f;
        smv[m * QS_STRIDE + d] = f2tf32(v);
    }
    __syncthreads();

    unsigned qf[6][4];
    {
        int r0 = wid * 16 + fr;
        #pragma unroll
        for (int kt = 0; kt < 6; kt++) {
            qf[kt][0] = smv[r0 * QS_STRIDE + kt * 8 + fk];
            qf[kt][1] = smv[(r0 + 8) * QS_STRIDE + kt * 8 + fk];
            qf[kt][2] = smv[r0 * QS_STRIDE + kt * 8 + fk + 4];
            qf[kt][3] = smv[(r0 + 8) * QS_STRIDE + kt * 8 + fk + 4];
        }
    }
    __syncthreads();   // all qf reads done before ring fills overwrite Q area

    uint32_t sm_sh = (uint32_t)__cvta_generic_to_shared(smv);

    // prologue: chunks 0,1 -> stages 0,1
    attn_fill(sm_sh, tid, kbase, vbase, 0, 0);
    attn_fill(sm_sh, tid, kbase, vbase, 1, 1);

    float oacc[6][4];
    #pragma unroll
    for (int j = 0; j < 6; j++)
        #pragma unroll
        for (int r = 0; r < 4; r++) oacc[j][r] = 0.0f;
    float lsum[2] = {0.f, 0.f};

    // K ldmatrix per-thread column offset (row = key, col = d-words)
    uint32_t kcol_off = (uint32_t)(((g >> 1) * 8 + (g & 1) * 4) * 4);
    // V ldmatrix per-thread row offset
    int vm = lane >> 3, vr = lane & 7;
    uint32_t vrow_off = (uint32_t)(((((vm >> 1) << 3) + vr) * VS_STRIDE + (vm & 1) * 4) * 4);
    // P shuffle source lane
    int psrc = (lane & 28) | (fk >> 1);
    bool podd = (fk & 1) != 0;

    for (int c = 0; c < 49; c++) {
        if (c >= 47) { CP_WAIT0(); } else { CP_WAIT1(); }
        __syncthreads();   // all warps done with chunk c-1 -> its stage is free

        if (c + 2 < 49)
            attn_fill(sm_sh, tid, kbase, vbase, c + 2, (c + 2) % 3);

        uint32_t kb_sh = sm_sh + (uint32_t)(((c % 3) * STAGEW) * 4);
        uint32_t vb_sh = kb_sh + (uint32_t)(KS_BUFW * 4) + vrow_off;

        for (int sub = 0; sub < 8; sub++) {
            // ---- QK: K-frags via ldmatrix (rows = 8 keys of sub) ----
            float s0[4] = {0.f, 0.f, 0.f, 0.f};
            uint32_t krow = kb_sh + (uint32_t)(((sub * 8 + lr) * KS_STRIDE) * 4) + kcol_off;
            #pragma unroll
            for (int jp = 0; jp < 3; jp++) {
                unsigned bk0[2], bk1[2];
                ldsm_x4(bk0[0], bk0[1], bk1[0], bk1[1],
                        krow + (uint32_t)(jp * 64));   // 16 words per kt-pair
                mma_tf32(s0, qf[2 * jp], bk0);
                mma_tf32(s0, qf[2 * jp + 1], bk1);
            }
            // ---- exp (tf32) + lsum ----
            unsigned c0 = f2tf32(__expf(s0[0]));
            unsigned c1 = f2tf32(__expf(s0[1]));
            unsigned c2 = f2tf32(__expf(s0[2]));
            unsigned c3 = f2tf32(__expf(s0[3]));
            lsum[0] += __uint_as_float(c0) + __uint_as_float(c1);
            lsum[1] += __uint_as_float(c2) + __uint_as_float(c3);
            // ---- P C-frag -> A-frag via shuffles (no smem, no syncwarp) ----
            unsigned u0 = __shfl_sync(0xffffffffu, c0, psrc);
            unsigned u1 = __shfl_sync(0xffffffffu, c1, psrc);
            unsigned u2 = __shfl_sync(0xffffffffu, c2, psrc);
            unsigned u3 = __shfl_sync(0xffffffffu, c3, psrc);
            unsigned w0 = __shfl_sync(0xffffffffu, c0, psrc + 2);
            unsigned w1 = __shfl_sync(0xffffffffu, c1, psrc + 2);
            unsigned w2 = __shfl_sync(0xffffffffu, c2, psrc + 2);
            unsigned w3 = __shfl_sync(0xffffffffu, c3, psrc + 2);
            unsigned pa[4];
            pa[0] = podd ? u1 : u0;
            pa[1] = podd ? u3 : u2;
            pa[2] = podd ? w1 : w0;
            pa[3] = podd ? w3 : w2;
            // ---- PV: V-frags via ldmatrix on transposed V [d][key] ----
            uint32_t vaddr = vb_sh + (uint32_t)(sub * 32);
            #pragma unroll
            for (int p = 0; p < 3; p++) {
                unsigned v0[2], v1[2];
                ldsm_x4(v0[0], v0[1], v1[0], v1[1],
                        vaddr + (uint32_t)(p * (16 * VS_STRIDE * 4)));
                mma_tf32(oacc[2 * p], pa, v0);
                mma_tf32(oacc[2 * p + 1], pa, v1);
            }
        }
    }

    // ---- epilogue ----
    #pragma unroll
    for (int hh = 0; hh < 2; hh++) {
        float l = lsum[hh];
        l += __shfl_xor_sync(0xffffffffu, l, 1);
        l += __shfl_xor_sync(0xffffffffu, l, 2);
        float inv = 1.0f / l;
        int m = wid * 16 + fr + hh * 8;
        if (m < M_) {
            float* orow = g_ao + ((size_t)b * M_ + m) * C_ + h * DH_;
            #pragma unroll
            for (int nt = 0; nt < 6; nt++) {
                float2 val;
                val.x = rtf32(oacc[nt][hh * 2 + 0] * inv);
                val.y = rtf32(oacc[nt][hh * 2 + 1] * inv);
                *(float2*)(orow + nt * 8 + 2 * fk) = val;
            }
        }
    }
}

// ----------------------------------------------------------------- launcher
extern "C" void kernel_launch(void* const* d_in, const int* in_sizes, int n_in,
                              void* d_out, int out_size)
{
    const float* x      = (const float*)d_in[0];
    const float* qp     = (const float*)d_in[1];
    const float* kv_w   = (const float*)d_in[2];
    const float* proj_w = (const float*)d_in[3];
    const float* proj_b = (const float*)d_in[4];
    const float* ln_w   = (const float*)d_in[5];
    const float* ln_b   = (const float*)d_in[6];
    float* out = (float*)d_out;

    cudaFuncSetAttribute(attn_mma_kernel,
                         cudaFuncAttributeMaxDynamicSharedMemorySize, AT_SMEMW * 4);
    cudaFuncSetAttribute(mma_kv_kernel,
                         cudaFuncAttributeMaxDynamicSharedMemorySize, GSMEMB);
    cudaFuncSetAttribute(mma_proj_kernel,
                         cudaFuncAttributeMaxDynamicSharedMemorySize, GSMEMB);

    round_w_kernel<<<(2 * C_ * C_ + 255) / 256, 256>>>(kv_w, proj_w);

    ln_gelu_kernel<<<T_ / 8, 256>>>(x, ln_w, ln_b);

    dim3 g2(6, 784);
    mma_kv_kernel<<<g2, 256, GSMEMB>>>();

    attn_mma_kernel<<<B_ * H_, AT_THREADS, AT_SMEMW * 4>>>(qp);

    dim3 g4(3, 49);
    mma_proj_kernel<<<g4, 256, GSMEMB>>>(proj_b, out);
}

// round 15
// speedup vs baseline: 1.1671x; 1.0418x over previous
#include <cuda_runtime.h>
#include <math.h>
#include <stdint.h>

// Problem dims
#define B_   32
#define N_   3136
#define C_   384
#define H_   8
#define DH_  48
#define M_   196
#define T_   (B_ * N_)          // 100352 tokens

// ---------------- scratch (static device globals; no runtime allocation) ---
__device__ float g_xg[T_ * C_];              // gelu(ln(x)), tf32-valued
__device__ float g_k [B_ * H_ * N_ * DH_];   // k [b,h,n,d], tf32-valued
__device__ float g_v [B_ * H_ * DH_ * N_];   // v [b,h,d,n] (TRANSPOSED), tf32-valued
__device__ float g_ao[B_ * M_ * C_];         // attn out [b,m,c], tf32-valued
__device__ float g_wkv[2 * C_ * C_];         // kv_w pre-rounded to tf32
__device__ float g_wpj[C_ * C_];             // proj_w pre-rounded to tf32

// ------------------------------------------------------ tf32 helpers
__device__ __forceinline__ unsigned f2tf32(float f) {
    unsigned r;
    asm("cvt.rna.tf32.f32 %0, %1;" : "=r"(r) : "f"(f));
    return r;
}
__device__ __forceinline__ float rtf32(float f) { return __uint_as_float(f2tf32(f)); }

__device__ __forceinline__ void mma_tf32(float* c, const unsigned* a, const unsigned* b) {
    asm volatile(
        "mma.sync.aligned.m16n8k8.row.col.f32.tf32.tf32.f32 "
        "{%0,%1,%2,%3}, {%4,%5,%6,%7}, {%8,%9}, {%0,%1,%2,%3};"
        : "+f"(c[0]), "+f"(c[1]), "+f"(c[2]), "+f"(c[3])
        : "r"(a[0]), "r"(a[1]), "r"(a[2]), "r"(a[3]),
          "r"(b[0]), "r"(b[1]));
}

// ldmatrix x4 on 32-bit (tf32) data viewed as b16 pairs.
__device__ __forceinline__ void ldsm_x4(unsigned &r0, unsigned &r1,
                                        unsigned &r2, unsigned &r3, uint32_t addr) {
    asm volatile("ldmatrix.sync.aligned.m8n8.x4.shared.b16 {%0,%1,%2,%3}, [%4];"
        : "=r"(r0), "=r"(r1), "=r"(r2), "=r"(r3) : "r"(addr));
}

__device__ __forceinline__ void cp16(uint32_t sa, const void* g) {
    asm volatile("cp.async.cg.shared.global [%0], [%1], 16;" :: "r"(sa), "l"(g));
}
#define CP_COMMIT() asm volatile("cp.async.commit_group;")
#define CP_WAIT1()  asm volatile("cp.async.wait_group 1;")
#define CP_WAIT0()  asm volatile("cp.async.wait_group 0;")

// ------------------------------------------------- K0: pre-round weights
__global__ __launch_bounds__(256) void round_w_kernel(
    const float* __restrict__ kv_w, const float* __restrict__ proj_w)
{
    int i = blockIdx.x * 256 + threadIdx.x;
    if (i < 2 * C_ * C_) g_wkv[i] = rtf32(kv_w[i]);
    if (i < C_ * C_)     g_wpj[i] = rtf32(proj_w[i]);
}

// ---------------------------------------------------------------- K1: LN+GELU
__global__ __launch_bounds__(256) void ln_gelu_kernel(
    const float* __restrict__ x,
    const float* __restrict__ lw,
    const float* __restrict__ lb)
{
    int t = (blockIdx.x * 256 + threadIdx.x) >> 5;
    int lane = threadIdx.x & 31;
    const float4* xr = (const float4*)(x + (size_t)t * C_);
    float4* outr = (float4*)(g_xg + (size_t)t * C_);

    float4 a = xr[lane], bq = xr[lane + 32], cq = xr[lane + 64];
    float s = a.x + a.y + a.z + a.w + bq.x + bq.y + bq.z + bq.w
            + cq.x + cq.y + cq.z + cq.w;
    float q = a.x*a.x + a.y*a.y + a.z*a.z + a.w*a.w
            + bq.x*bq.x + bq.y*bq.y + bq.z*bq.z + bq.w*bq.w
            + cq.x*cq.x + cq.y*cq.y + cq.z*cq.z + cq.w*cq.w;
    #pragma unroll
    for (int o = 16; o > 0; o >>= 1) {
        s += __shfl_xor_sync(0xffffffffu, s, o);
        q += __shfl_xor_sync(0xffffffffu, q, o);
    }
    float mu  = s * (1.0f / C_);
    float var = q * (1.0f / C_) - mu * mu;
    float rs  = rsqrtf(var + 1e-6f);

    const float4* lw4 = (const float4*)lw;
    const float4* lb4 = (const float4*)lb;
    #pragma unroll
    for (int j = 0; j < 3; j++) {
        float4 v = (j == 0) ? a : ((j == 1) ? bq : cq);
        float4 w = lw4[lane + j * 32];
        float4 bb = lb4[lane + j * 32];
        float4 o;
        float y;
        y = (v.x - mu) * rs * w.x + bb.x;
        o.x = rtf32(0.5f * y * (1.0f + erff(y * 0.70710678118654752f)));
        y = (v.y - mu) * rs * w.y + bb.y;
        o.y = rtf32(0.5f * y * (1.0f + erff(y * 0.70710678118654752f)));
        y = (v.z - mu) * rs * w.z + bb.z;
        o.z = rtf32(0.5f * y * (1.0f + erff(y * 0.70710678118654752f)));
        y = (v.w - mu) * rs * w.w + bb.w;
        o.w = rtf32(0.5f * y * (1.0f + erff(y * 0.70710678118654752f)));
        outr[lane + j * 32] = o;
    }
}

// ============= shared 3-stage pipelined tf32 GEMM core (128x128 CTA) =========
// k-chunk 32 (half the barriers of the R12 core). A,B tiles [row][k] stride 36
// (frag LDS bank = 4*fr+fk+kp mod 32: conflict-free). 108 KB smem, 2 CTAs/SM.
#define GSTRIDE 36
#define GSTAGEW (128 * GSTRIDE)      // 4608 words per stage per matrix
#define GBOFF   (3 * GSTAGEW)
#define GSMEMB  (6 * GSTAGEW * 4)    // 110592 bytes

__device__ __forceinline__ void gemm_cp_chunk(
    float* sm, int stage, int tid, const float* Abase, const float* Bbase, int c)
{
    float* as = sm + stage * GSTAGEW;
    float* bs = sm + GBOFF + stage * GSTAGEW;
    #pragma unroll
    for (int j = 0; j < 4; j++) {
        int cidx = tid + j * 256;           // 0..1023
        int row = cidx >> 3, kq = cidx & 7; // 8 x 16B units per row
        cp16((uint32_t)__cvta_generic_to_shared(as + row * GSTRIDE + kq * 4),
             Abase + (size_t)row * C_ + c * 32 + kq * 4);
        cp16((uint32_t)__cvta_generic_to_shared(bs + row * GSTRIDE + kq * 4),
             Bbase + (size_t)row * C_ + c * 32 + kq * 4);
    }
    CP_COMMIT();
}

__device__ __forceinline__ void gemm_mainloop(
    float* sm, int tid, const float* Abase, const float* Bbase,
    float acc[4][4][4], int wm, int wn, int fr, int fk)
{
    gemm_cp_chunk(sm, 0, tid, Abase, Bbase, 0);
    gemm_cp_chunk(sm, 1, tid, Abase, Bbase, 1);

    for (int c = 0; c < 12; c++) {
        if (c >= 10) { CP_WAIT0(); } else { CP_WAIT1(); }
        __syncthreads();
        const unsigned* As = (const unsigned*)(sm + (c % 3) * GSTAGEW);
        const unsigned* Bs = (const unsigned*)(sm + GBOFF + (c % 3) * GSTAGEW);

        #pragma unroll
        for (int kp = 0; kp < 32; kp += 8) {
            unsigned af[4][4];
            #pragma unroll
            for (int mt = 0; mt < 4; mt++) {
                int rb = wm * 64 + mt * 16 + fr;
                af[mt][0] = As[rb * GSTRIDE + kp + fk];
                af[mt][1] = As[(rb + 8) * GSTRIDE + kp + fk];
                af[mt][2] = As[rb * GSTRIDE + kp + fk + 4];
                af[mt][3] = As[(rb + 8) * GSTRIDE + kp + fk + 4];
            }
            unsigned bf[4][2];
            #pragma unroll
            for (int nt = 0; nt < 4; nt++) {
                int cb = wn * 32 + nt * 8 + fr;
                bf[nt][0] = Bs[cb * GSTRIDE + kp + fk];
                bf[nt][1] = Bs[cb * GSTRIDE + kp + fk + 4];
            }
            #pragma unroll
            for (int mt = 0; mt < 4; mt++)
                #pragma unroll
                for (int nt = 0; nt < 4; nt++)
                    mma_tf32(acc[mt][nt], af[mt], bf[nt]);
        }

        if (c + 2 < 12)
            gemm_cp_chunk(sm, (c + 2) % 3, tid, Abase, Bbase, c + 2);
    }
}

// --------------------------------------------------------- K2: kv GEMM (tf32)
// k epilogue -> g_k [b,h,n,d]; v epilogue -> g_v [b,h,d,n] (transposed).
__global__ void __launch_bounds__(256, 2) mma_kv_kernel()
{
    extern __shared__ float sm[];
    int n0 = blockIdx.x * 128;
    int m0 = blockIdx.y * 128;
    int tid = threadIdx.x;
    int wid = tid >> 5, lane = tid & 31;
    int wm = wid >> 2, wn = wid & 3;
    int fr = lane >> 2, fk = lane & 3;

    float acc[4][4][4];
    #pragma unroll
    for (int i = 0; i < 4; i++)
        #pragma unroll
        for (int j = 0; j < 4; j++)
            #pragma unroll
            for (int r = 0; r < 4; r++) acc[i][j][r] = 0.0f;

    gemm_mainloop(sm, tid, g_xg + (size_t)m0 * C_, g_wkv + (size_t)n0 * C_,
                  acc, wm, wn, fr, fk);

    #pragma unroll
    for (int mt = 0; mt < 4; mt++) {
        #pragma unroll
        for (int half = 0; half < 2; half++) {
            int r  = m0 + wm * 64 + mt * 16 + fr + half * 8;
            int bb = r / N_;
            int nn = r - bb * N_;
            #pragma unroll
            for (int nt = 0; nt < 4; nt++) {
                int c  = n0 + wn * 32 + nt * 8 + fk * 2;
                float vx = rtf32(acc[mt][nt][half * 2 + 0]);
                float vy = rtf32(acc[mt][nt][half * 2 + 1]);
                if (c < C_) {
                    int h  = c / DH_;
                    int d  = c - h * DH_;
                    float2 val; val.x = vx; val.y = vy;
                    *(float2*)(g_k + (((size_t)bb * H_ + h) * N_ + nn) * DH_ + d) = val;
                } else {
                    int cc = c - C_;
                    int h  = cc / DH_;
                    int d  = cc - h * DH_;
                    float* dst = g_v + (((size_t)bb * H_ + h) * DH_ + d) * N_ + nn;
                    dst[0]  = vx;
                    dst[N_] = vy;
                }
            }
        }
    }
}

// -------------------------------------------------------------- K4: proj GEMM
__global__ void __launch_bounds__(256, 2) mma_proj_kernel(
    const float* __restrict__ bias,
    float* __restrict__ out)
{
    extern __shared__ float sm[];
    int n0 = blockIdx.x * 128;
    int m0 = blockIdx.y * 128;
    int tid = threadIdx.x;
    int wid = tid >> 5, lane = tid & 31;
    int wm = wid >> 2, wn = wid & 3;
    int fr = lane >> 2, fk = lane & 3;

    float acc[4][4][4];
    #pragma unroll
    for (int i = 0; i < 4; i++)
        #pragma unroll
        for (int j = 0; j < 4; j++)
            #pragma unroll
            for (int r = 0; r < 4; r++) acc[i][j][r] = 0.0f;

    gemm_mainloop(sm, tid, g_ao + (size_t)m0 * C_, g_wpj + (size_t)n0 * C_,
                  acc, wm, wn, fr, fk);

    #pragma unroll
    for (int mt = 0; mt < 4; mt++) {
        #pragma unroll
        for (int half = 0; half < 2; half++) {
            int r = m0 + wm * 64 + mt * 16 + fr + half * 8;
            #pragma unroll
            for (int nt = 0; nt < 4; nt++) {
                int c = n0 + wn * 32 + nt * 8 + fk * 2;
                float2 val;
                val.x = acc[mt][nt][half * 2 + 0] + bias[c];
                val.y = acc[mt][nt][half * 2 + 1] + bias[c + 1];
                *(float2*)(out + (size_t)r * C_ + c) = val;
            }
        }
    }
}

// ------------------------------------------------------------- K3: MMA attn
// 13 warps (416 thr), one 16-row M-tile per warp, 2 CTAs/SM.
// Triple-buffered K/V ring, ONE barrier per chunk, P remap via shuffles,
// QK accumulation split into two independent chains (depth 6 -> 3).
#define AT_THREADS 416
#define QROWS 208
#define QS_STRIDE 52
#define KS_STRIDE 52
#define KS_BUFW 3328            // 64*52
#define VS_STRIDE 68            // 64 keys + 4 pad
#define VS_BUFW 3264            // 48*68
#define STAGEW  (KS_BUFW + VS_BUFW)   // 6592 words per ring stage
#define AT_SMEMW (3 * STAGEW)         // 19776 words (79104 B)

__device__ __forceinline__ void attn_fill(
    uint32_t sm_sh, int tid, const float* kbase, const float* vbase, int c, int s)
{
    uint32_t stb = sm_sh + (uint32_t)(s * STAGEW * 4);
    const float4* ks = (const float4*)(kbase + (size_t)c * 64 * DH_);
    for (int cidx = tid; cidx < 768; cidx += AT_THREADS) {
        int r = cidx / 12, cc = cidx - r * 12;
        cp16(stb + (uint32_t)((r * KS_STRIDE + cc * 4) * 4), ks + cidx);
    }
    const float* vsb = vbase + c * 64;
    for (int cidx = tid; cidx < 768; cidx += AT_THREADS) {
        int d = cidx >> 4, u = cidx & 15;
        cp16(stb + (uint32_t)((KS_BUFW + d * VS_STRIDE + u * 4) * 4),
             vsb + (size_t)d * N_ + u * 4);
    }
    CP_COMMIT();
}

__global__ void __launch_bounds__(AT_THREADS, 2) attn_mma_kernel(const float* __restrict__ qp)
{
    extern __shared__ uint32_t smv[];
    int tid = threadIdx.x;
    int bh = blockIdx.x;
    int b = bh >> 3, h = bh & 7;
    int wid = tid >> 5, lane = tid & 31;
    int fr = lane >> 2, fk = lane & 3;
    int g = lane >> 3, lr = lane & 7;

    const float* kbase = g_k + (size_t)bh * N_ * DH_;
    const float* vbase = g_v + (size_t)bh * DH_ * N_;

    for (int idx = tid; idx < QROWS * 48; idx += AT_THREADS) {
        int m = idx / 48, d = idx - m * 48;
        float v = (m < M_) ? qp[((size_t)m * H_ + h) * DH_ + d] : 0.0f;
        smv[m * QS_STRIDE + d] = f2tf32(v);
    }
    __syncthreads();

    unsigned qf[6][4];
    {
        int r0 = wid * 16 + fr;
        #pragma unroll
        for (int kt = 0; kt < 6; kt++) {
            qf[kt][0] = smv[r0 * QS_STRIDE + kt * 8 + fk];
            qf[kt][1] = smv[(r0 + 8) * QS_STRIDE + kt * 8 + fk];
            qf[kt][2] = smv[r0 * QS_STRIDE + kt * 8 + fk + 4];
            qf[kt][3] = smv[(r0 + 8) * QS_STRIDE + kt * 8 + fk + 4];
        }
    }
    __syncthreads();

    uint32_t sm_sh = (uint32_t)__cvta_generic_to_shared(smv);

    attn_fill(sm_sh, tid, kbase, vbase, 0, 0);
    attn_fill(sm_sh, tid, kbase, vbase, 1, 1);

    float oacc[6][4];
    #pragma unroll
    for (int j = 0; j < 6; j++)
        #pragma unroll
        for (int r = 0; r < 4; r++) oacc[j][r] = 0.0f;
    float lsum[2] = {0.f, 0.f};

    uint32_t kcol_off = (uint32_t)(((g >> 1) * 8 + (g & 1) * 4) * 4);
    int vm = lane >> 3, vr = lane & 7;
    uint32_t vrow_off = (uint32_t)(((((vm >> 1) << 3) + vr) * VS_STRIDE + (vm & 1) * 4) * 4);
    int psrc = (lane & 28) | (fk >> 1);
    bool podd = (fk & 1) != 0;

    for (int c = 0; c < 49; c++) {
        if (c >= 47) { CP_WAIT0(); } else { CP_WAIT1(); }
        __syncthreads();

        if (c + 2 < 49)
            attn_fill(sm_sh, tid, kbase, vbase, c + 2, (c + 2) % 3);

        uint32_t kb_sh = sm_sh + (uint32_t)(((c % 3) * STAGEW) * 4);
        uint32_t vb_sh = kb_sh + (uint32_t)(KS_BUFW * 4) + vrow_off;

        for (int sub = 0; sub < 8; sub++) {
            // ---- QK: two independent accumulation chains ----
            float sa[4] = {0.f, 0.f, 0.f, 0.f};
            float sb[4] = {0.f, 0.f, 0.f, 0.f};
            uint32_t krow = kb_sh + (uint32_t)(((sub * 8 + lr) * KS_STRIDE) * 4) + kcol_off;
            #pragma unroll
            for (int jp = 0; jp < 3; jp++) {
                unsigned bk0[2], bk1[2];
                ldsm_x4(bk0[0], bk0[1], bk1[0], bk1[1],
                        krow + (uint32_t)(jp * 64));
                mma_tf32(sa, qf[2 * jp], bk0);
                mma_tf32(sb, qf[2 * jp + 1], bk1);
            }
            // ---- exp (tf32) + lsum ----
            unsigned c0 = f2tf32(__expf(sa[0] + sb[0]));
            unsigned c1 = f2tf32(__expf(sa[1] + sb[1]));
            unsigned c2 = f2tf32(__expf(sa[2] + sb[2]));
            unsigned c3 = f2tf32(__expf(sa[3] + sb[3]));
            lsum[0] += __uint_as_float(c0) + __uint_as_float(c1);
            lsum[1] += __uint_as_float(c2) + __uint_as_float(c3);
            // ---- P C-frag -> A-frag via shuffles ----
            unsigned u0 = __shfl_sync(0xffffffffu, c0, psrc);
            unsigned u1 = __shfl_sync(0xffffffffu, c1, psrc);
            unsigned u2 = __shfl_sync(0xffffffffu, c2, psrc);
            unsigned u3 = __shfl_sync(0xffffffffu, c3, psrc);
            unsigned w0 = __shfl_sync(0xffffffffu, c0, psrc + 2);
            unsigned w1 = __shfl_sync(0xffffffffu, c1, psrc + 2);
            unsigned w2 = __shfl_sync(0xffffffffu, c2, psrc + 2);
            unsigned w3 = __shfl_sync(0xffffffffu, c3, psrc + 2);
            unsigned pa[4];
            pa[0] = podd ? u1 : u0;
            pa[1] = podd ? u3 : u2;
            pa[2] = podd ? w1 : w0;
            pa[3] = podd ? w3 : w2;
            // ---- PV: V-frags via ldmatrix on transposed V [d][key] ----
            uint32_t vaddr = vb_sh + (uint32_t)(sub * 32);
            #pragma unroll
            for (int p = 0; p < 3; p++) {
                unsigned v0[2], v1[2];
                ldsm_x4(v0[0], v0[1], v1[0], v1[1],
                        vaddr + (uint32_t)(p * (16 * VS_STRIDE * 4)));
                mma_tf32(oacc[2 * p], pa, v0);
                mma_tf32(oacc[2 * p + 1], pa, v1);
            }
        }
    }

    // ---- epilogue ----
    #pragma unroll
    for (int hh = 0; hh < 2; hh++) {
        float l = lsum[hh];
        l += __shfl_xor_sync(0xffffffffu, l, 1);
        l += __shfl_xor_sync(0xffffffffu, l, 2);
        float inv = 1.0f / l;
        int m = wid * 16 + fr + hh * 8;
        if (m < M_) {
            float* orow = g_ao + ((size_t)b * M_ + m) * C_ + h * DH_;
            #pragma unroll
            for (int nt = 0; nt < 6; nt++) {
                float2 val;
                val.x = rtf32(oacc[nt][hh * 2 + 0] * inv);
                val.y = rtf32(oacc[nt][hh * 2 + 1] * inv);
                *(float2*)(orow + nt * 8 + 2 * fk) = val;
            }
        }
    }
}

// ----------------------------------------------------------------- launcher
extern "C" void kernel_launch(void* const* d_in, const int* in_sizes, int n_in,
                              void* d_out, int out_size)
{
    const float* x      = (const float*)d_in[0];
    const float* qp     = (const float*)d_in[1];
    const float* kv_w   = (const float*)d_in[2];
    const float* proj_w = (const float*)d_in[3];
    const float* proj_b = (const float*)d_in[4];
    const float* ln_w   = (const float*)d_in[5];
    const float* ln_b   = (const float*)d_in[6];
    float* out = (float*)d_out;

    cudaFuncSetAttribute(attn_mma_kernel,
                         cudaFuncAttributeMaxDynamicSharedMemorySize, AT_SMEMW * 4);
    cudaFuncSetAttribute(mma_kv_kernel,
                         cudaFuncAttributeMaxDynamicSharedMemorySize, GSMEMB);
    cudaFuncSetAttribute(mma_proj_kernel,
                         cudaFuncAttributeMaxDynamicSharedMemorySize, GSMEMB);

    round_w_kernel<<<(2 * C_ * C_ + 255) / 256, 256>>>(kv_w, proj_w);

    ln_gelu_kernel<<<T_ / 8, 256>>>(x, ln_w, ln_b);

    dim3 g2(6, 784);
    mma_kv_kernel<<<g2, 256, GSMEMB>>>();

    attn_mma_kernel<<<B_ * H_, AT_THREADS, AT_SMEMW * 4>>>(qp);

    dim3 g4(3, 49);
    mma_proj_kernel<<<g4, 256, GSMEMB>>>(proj_b, out);
}

// round 16
// speedup vs baseline: 1.2620x; 1.0813x over previous
#include <cuda_runtime.h>
#include <cuda_bf16.h>
#include <math.h>
#include <stdint.h>

// Problem dims
#define B_   32
#define N_   3136
#define C_   384
#define H_   8
#define DH_  48
#define M_   196
#define T_   (B_ * N_)          // 100352 tokens

// ---------------- scratch (static device globals; no runtime allocation) ---
__device__ float g_xg[T_ * C_];                   // gelu(ln(x)), tf32-valued
__device__ __nv_bfloat16 g_kh[B_ * H_ * N_ * DH_]; // k [b,h,n,d] in bf16
__device__ float g_v [B_ * H_ * DH_ * N_];        // v [b,h,d,n] transposed, tf32
__device__ float g_ao[B_ * M_ * C_];              // attn out [b,m,c], tf32-valued
__device__ float g_wkv[2 * C_ * C_];              // kv_w pre-rounded to tf32
__device__ float g_wpj[C_ * C_];                  // proj_w pre-rounded to tf32

// ------------------------------------------------------ helpers
__device__ __forceinline__ unsigned f2tf32(float f) {
    unsigned r;
    asm("cvt.rna.tf32.f32 %0, %1;" : "=r"(r) : "f"(f));
    return r;
}
__device__ __forceinline__ float rtf32(float f) { return __uint_as_float(f2tf32(f)); }

__device__ __forceinline__ void mma_tf32(float* c, const unsigned* a, const unsigned* b) {
    asm volatile(
        "mma.sync.aligned.m16n8k8.row.col.f32.tf32.tf32.f32 "
        "{%0,%1,%2,%3}, {%4,%5,%6,%7}, {%8,%9}, {%0,%1,%2,%3};"
        : "+f"(c[0]), "+f"(c[1]), "+f"(c[2]), "+f"(c[3])
        : "r"(a[0]), "r"(a[1]), "r"(a[2]), "r"(a[3]),
          "r"(b[0]), "r"(b[1]));
}
__device__ __forceinline__ void mma_bf16(float* c, const unsigned* a, const unsigned* b) {
    asm volatile(
        "mma.sync.aligned.m16n8k16.row.col.f32.bf16.bf16.f32 "
        "{%0,%1,%2,%3}, {%4,%5,%6,%7}, {%8,%9}, {%0,%1,%2,%3};"
        : "+f"(c[0]), "+f"(c[1]), "+f"(c[2]), "+f"(c[3])
        : "r"(a[0]), "r"(a[1]), "r"(a[2]), "r"(a[3]),
          "r"(b[0]), "r"(b[1]));
}
// pack two f32 -> bf16x2 (lo = first arg, hi = second arg)
__device__ __forceinline__ unsigned pack_bf16(float lo, float hi) {
    unsigned r;
    asm("cvt.rn.bf16x2.f32 %0, %1, %2;" : "=r"(r) : "f"(hi), "f"(lo));
    return r;
}

__device__ __forceinline__ void ldsm_x4(unsigned &r0, unsigned &r1,
                                        unsigned &r2, unsigned &r3, uint32_t addr) {
    asm volatile("ldmatrix.sync.aligned.m8n8.x4.shared.b16 {%0,%1,%2,%3}, [%4];"
        : "=r"(r0), "=r"(r1), "=r"(r2), "=r"(r3) : "r"(addr));
}
__device__ __forceinline__ void ldsm_x2(unsigned &r0, unsigned &r1, uint32_t addr) {
    asm volatile("ldmatrix.sync.aligned.m8n8.x2.shared.b16 {%0,%1}, [%2];"
        : "=r"(r0), "=r"(r1) : "r"(addr));
}

__device__ __forceinline__ void cp16(uint32_t sa, const void* g) {
    asm volatile("cp.async.cg.shared.global [%0], [%1], 16;" :: "r"(sa), "l"(g));
}
#define CP_COMMIT() asm volatile("cp.async.commit_group;")
#define CP_WAIT1()  asm volatile("cp.async.wait_group 1;")
#define CP_WAIT0()  asm volatile("cp.async.wait_group 0;")

// ------------------------------------------------- K0: pre-round weights
__global__ __launch_bounds__(256) void round_w_kernel(
    const float* __restrict__ kv_w, const float* __restrict__ proj_w)
{
    int i = blockIdx.x * 256 + threadIdx.x;
    if (i < 2 * C_ * C_) g_wkv[i] = rtf32(kv_w[i]);
    if (i < C_ * C_)     g_wpj[i] = rtf32(proj_w[i]);
}

// ---------------------------------------------------------------- K1: LN+GELU
__global__ __launch_bounds__(256) void ln_gelu_kernel(
    const float* __restrict__ x,
    const float* __restrict__ lw,
    const float* __restrict__ lb)
{
    int t = (blockIdx.x * 256 + threadIdx.x) >> 5;
    int lane = threadIdx.x & 31;
    const float4* xr = (const float4*)(x + (size_t)t * C_);
    float4* outr = (float4*)(g_xg + (size_t)t * C_);

    float4 a = xr[lane], bq = xr[lane + 32], cq = xr[lane + 64];
    float s = a.x + a.y + a.z + a.w + bq.x + bq.y + bq.z + bq.w
            + cq.x + cq.y + cq.z + cq.w;
    float q = a.x*a.x + a.y*a.y + a.z*a.z + a.w*a.w
            + bq.x*bq.x + bq.y*bq.y + bq.z*bq.z + bq.w*bq.w
            + cq.x*cq.x + cq.y*cq.y + cq.z*cq.z + cq.w*cq.w;
    #pragma unroll
    for (int o = 16; o > 0; o >>= 1) {
        s += __shfl_xor_sync(0xffffffffu, s, o);
        q += __shfl_xor_sync(0xffffffffu, q, o);
    }
    float mu  = s * (1.0f / C_);
    float var = q * (1.0f / C_) - mu * mu;
    float rs  = rsqrtf(var + 1e-6f);

    const float4* lw4 = (const float4*)lw;
    const float4* lb4 = (const float4*)lb;
    #pragma unroll
    for (int j = 0; j < 3; j++) {
        float4 v = (j == 0) ? a : ((j == 1) ? bq : cq);
        float4 w = lw4[lane + j * 32];
        float4 bb = lb4[lane + j * 32];
        float4 o;
        float y;
        y = (v.x - mu) * rs * w.x + bb.x;
        o.x = rtf32(0.5f * y * (1.0f + erff(y * 0.70710678118654752f)));
        y = (v.y - mu) * rs * w.y + bb.y;
        o.y = rtf32(0.5f * y * (1.0f + erff(y * 0.70710678118654752f)));
        y = (v.z - mu) * rs * w.z + bb.z;
        o.z = rtf32(0.5f * y * (1.0f + erff(y * 0.70710678118654752f)));
        y = (v.w - mu) * rs * w.w + bb.w;
        o.w = rtf32(0.5f * y * (1.0f + erff(y * 0.70710678118654752f)));
        outr[lane + j * 32] = o;
    }
}

// ============= shared 3-stage pipelined tf32 GEMM core (128x128 CTA) =========
// k-chunk 32 (R15-validated). A,B tiles [row][k] stride 36.
#define GSTRIDE 36
#define GSTAGEW (128 * GSTRIDE)
#define GBOFF   (3 * GSTAGEW)
#define GSMEMB  (6 * GSTAGEW * 4)    // 110592 bytes

__device__ __forceinline__ void gemm_cp_chunk(
    float* sm, int stage, int tid, const float* Abase, const float* Bbase, int c)
{
    float* as = sm + stage * GSTAGEW;
    float* bs = sm + GBOFF + stage * GSTAGEW;
    #pragma unroll
    for (int j = 0; j < 4; j++) {
        int cidx = tid + j * 256;
        int row = cidx >> 3, kq = cidx & 7;
        cp16((uint32_t)__cvta_generic_to_shared(as + row * GSTRIDE + kq * 4),
             Abase + (size_t)row * C_ + c * 32 + kq * 4);
        cp16((uint32_t)__cvta_generic_to_shared(bs + row * GSTRIDE + kq * 4),
             Bbase + (size_t)row * C_ + c * 32 + kq * 4);
    }
    CP_COMMIT();
}

__device__ __forceinline__ void gemm_mainloop(
    float* sm, int tid, const float* Abase, const float* Bbase,
    float acc[4][4][4], int wm, int wn, int fr, int fk)
{
    gemm_cp_chunk(sm, 0, tid, Abase, Bbase, 0);
    gemm_cp_chunk(sm, 1, tid, Abase, Bbase, 1);

    for (int c = 0; c < 12; c++) {
        if (c >= 10) { CP_WAIT0(); } else { CP_WAIT1(); }
        __syncthreads();
        const unsigned* As = (const unsigned*)(sm + (c % 3) * GSTAGEW);
        const unsigned* Bs = (const unsigned*)(sm + GBOFF + (c % 3) * GSTAGEW);

        #pragma unroll
        for (int kp = 0; kp < 32; kp += 8) {
            unsigned af[4][4];
            #pragma unroll
            for (int mt = 0; mt < 4; mt++) {
                int rb = wm * 64 + mt * 16 + fr;
                af[mt][0] = As[rb * GSTRIDE + kp + fk];
                af[mt][1] = As[(rb + 8) * GSTRIDE + kp + fk];
                af[mt][2] = As[rb * GSTRIDE + kp + fk + 4];
                af[mt][3] = As[(rb + 8) * GSTRIDE + kp + fk + 4];
            }
            unsigned bf[4][2];
            #pragma unroll
            for (int nt = 0; nt < 4; nt++) {
                int cb = wn * 32 + nt * 8 + fr;
                bf[nt][0] = Bs[cb * GSTRIDE + kp + fk];
                bf[nt][1] = Bs[cb * GSTRIDE + kp + fk + 4];
            }
            #pragma unroll
            for (int mt = 0; mt < 4; mt++)
                #pragma unroll
                for (int nt = 0; nt < 4; nt++)
                    mma_tf32(acc[mt][nt], af[mt], bf[nt]);
        }

        if (c + 2 < 12)
            gemm_cp_chunk(sm, (c + 2) % 3, tid, Abase, Bbase, c + 2);
    }
}

// --------------------------------------------------------- K2: kv GEMM (tf32)
// k epilogue -> g_kh [b,h,n,d] bf16; v epilogue -> g_v [b,h,d,n] f32 (tf32).
__global__ void __launch_bounds__(256, 2) mma_kv_kernel()
{
    extern __shared__ float sm[];
    int n0 = blockIdx.x * 128;
    int m0 = blockIdx.y * 128;
    int tid = threadIdx.x;
    int wid = tid >> 5, lane = tid & 31;
    int wm = wid >> 2, wn = wid & 3;
    int fr = lane >> 2, fk = lane & 3;

    float acc[4][4][4];
    #pragma unroll
    for (int i = 0; i < 4; i++)
        #pragma unroll
        for (int j = 0; j < 4; j++)
            #pragma unroll
            for (int r = 0; r < 4; r++) acc[i][j][r] = 0.0f;

    gemm_mainloop(sm, tid, g_xg + (size_t)m0 * C_, g_wkv + (size_t)n0 * C_,
                  acc, wm, wn, fr, fk);

    #pragma unroll
    for (int mt = 0; mt < 4; mt++) {
        #pragma unroll
        for (int half = 0; half < 2; half++) {
            int r  = m0 + wm * 64 + mt * 16 + fr + half * 8;
            int bb = r / N_;
            int nn = r - bb * N_;
            #pragma unroll
            for (int nt = 0; nt < 4; nt++) {
                int c  = n0 + wn * 32 + nt * 8 + fk * 2;
                float vx = acc[mt][nt][half * 2 + 0];
                float vy = acc[mt][nt][half * 2 + 1];
                if (c < C_) {
                    int h  = c / DH_;
                    int d  = c - h * DH_;
                    __nv_bfloat162 kv2;
                    kv2.x = __float2bfloat16(vx);
                    kv2.y = __float2bfloat16(vy);
                    *(__nv_bfloat162*)(g_kh + (((size_t)bb * H_ + h) * N_ + nn) * DH_ + d) = kv2;
                } else {
                    int cc = c - C_;
                    int h  = cc / DH_;
                    int d  = cc - h * DH_;
                    float* dst = g_v + (((size_t)bb * H_ + h) * DH_ + d) * N_ + nn;
                    dst[0]  = rtf32(vx);
                    dst[N_] = rtf32(vy);
                }
            }
        }
    }
}

// -------------------------------------------------------------- K4: proj GEMM
__global__ void __launch_bounds__(256, 2) mma_proj_kernel(
    const float* __restrict__ bias,
    float* __restrict__ out)
{
    extern __shared__ float sm[];
    int n0 = blockIdx.x * 128;
    int m0 = blockIdx.y * 128;
    int tid = threadIdx.x;
    int wid = tid >> 5, lane = tid & 31;
    int wm = wid >> 2, wn = wid & 3;
    int fr = lane >> 2, fk = lane & 3;

    float acc[4][4][4];
    #pragma unroll
    for (int i = 0; i < 4; i++)
        #pragma unroll
        for (int j = 0; j < 4; j++)
            #pragma unroll
            for (int r = 0; r < 4; r++) acc[i][j][r] = 0.0f;

    gemm_mainloop(sm, tid, g_ao + (size_t)m0 * C_, g_wpj + (size_t)n0 * C_,
                  acc, wm, wn, fr, fk);

    #pragma unroll
    for (int mt = 0; mt < 4; mt++) {
        #pragma unroll
        for (int half = 0; half < 2; half++) {
            int r = m0 + wm * 64 + mt * 16 + fr + half * 8;
            #pragma unroll
            for (int nt = 0; nt < 4; nt++) {
                int c = n0 + wn * 32 + nt * 8 + fk * 2;
                float2 val;
                val.x = acc[mt][nt][half * 2 + 0] + bias[c];
                val.y = acc[mt][nt][half * 2 + 1] + bias[c + 1];
                *(float2*)(out + (size_t)r * C_ + c) = val;
            }
        }
    }
}

// ------------------------------------------------------------- K3: MMA attn
// 13 warps, one 16-row M-tile per warp, 2 CTAs/SM. Triple-buffered K/V ring,
// one barrier/chunk. QK in bf16 (m16n8k16, 3 MMAs/sub); PV in tf32.
// K smem bf16 [key][48+pad8] stride 112B; V smem f32 [d][key] stride 68 words.
#define AT_THREADS 416
#define QROWS 208
#define QS_STRIDE 52
#define KS_STRIDEB 112               // bytes per key row (56 bf16)
#define KS_BUFW 1792                 // words: 64*112/4
#define VS_STRIDE 68
#define VS_BUFW 3264                 // 48*68
#define STAGEW  (KS_BUFW + VS_BUFW)  // 5056 words
#define AT_SMEMW (3 * STAGEW)        // 15168 words (60672 B)

__device__ __forceinline__ void attn_fill(
    uint32_t sm_sh, int tid, const __nv_bfloat16* kbase, const float* vbase,
    int c, int s)
{
    uint32_t stb = sm_sh + (uint32_t)(s * STAGEW * 4);
    const __nv_bfloat16* ks = kbase + (size_t)c * 64 * DH_;
    for (int cidx = tid; cidx < 384; cidx += AT_THREADS) {
        int r = cidx / 6, u = cidx - r * 6;              // K: [key r][16B unit u]
        cp16(stb + (uint32_t)(r * KS_STRIDEB + u * 16), ks + r * DH_ + u * 8);
    }
    const float* vsb = vbase + c * 64;
    for (int cidx = tid; cidx < 768; cidx += AT_THREADS) {
        int d = cidx >> 4, u = cidx & 15;                // V: [d][key-unit u]
        cp16(stb + (uint32_t)((KS_BUFW + d * VS_STRIDE + u * 4) * 4),
             vsb + (size_t)d * N_ + u * 4);
    }
    CP_COMMIT();
}

__global__ void __launch_bounds__(AT_THREADS, 2) attn_mma_kernel(const float* __restrict__ qp)
{
    extern __shared__ uint32_t smv[];
    int tid = threadIdx.x;
    int bh = blockIdx.x;
    int b = bh >> 3, h = bh & 7;
    int wid = tid >> 5, lane = tid & 31;
    int fr = lane >> 2, fk = lane & 3;
    int g = lane >> 3, lr = lane & 7;

    const __nv_bfloat16* kbase = g_kh + (size_t)bh * N_ * DH_;
    const float* vbase = g_v + (size_t)bh * DH_ * N_;

    // ---- Q (raw f32) -> smem temp, then bf16 A-frags in regs ----
    float* smf = (float*)smv;
    for (int idx = tid; idx < QROWS * 48; idx += AT_THREADS) {
        int m = idx / 48, d = idx - m * 48;
        smf[m * QS_STRIDE + d] = (m < M_) ? qp[((size_t)m * H_ + h) * DH_ + d] : 0.0f;
    }
    __syncthreads();

    unsigned qf[3][4];     // bf16 A-frags: kstep kt covers d=16kt..16kt+15
    {
        int r0 = wid * 16 + fr;
        #pragma unroll
        for (int kt = 0; kt < 3; kt++) {
            int d0 = 16 * kt + 2 * fk;
            qf[kt][0] = pack_bf16(smf[r0 * QS_STRIDE + d0],       smf[r0 * QS_STRIDE + d0 + 1]);
            qf[kt][1] = pack_bf16(smf[(r0 + 8) * QS_STRIDE + d0], smf[(r0 + 8) * QS_STRIDE + d0 + 1]);
            qf[kt][2] = pack_bf16(smf[r0 * QS_STRIDE + d0 + 8],   smf[r0 * QS_STRIDE + d0 + 9]);
            qf[kt][3] = pack_bf16(smf[(r0 + 8) * QS_STRIDE + d0 + 8], smf[(r0 + 8) * QS_STRIDE + d0 + 9]);
        }
    }
    __syncthreads();   // qf built before ring fills overwrite Q area

    uint32_t sm_sh = (uint32_t)__cvta_generic_to_shared(smv);

    attn_fill(sm_sh, tid, kbase, vbase, 0, 0);
    attn_fill(sm_sh, tid, kbase, vbase, 1, 1);

    float oacc[6][4];
    #pragma unroll
    for (int j = 0; j < 6; j++)
        #pragma unroll
        for (int r = 0; r < 4; r++) oacc[j][r] = 0.0f;
    float lsum[2] = {0.f, 0.f};

    int vm = lane >> 3, vr = lane & 7;
    uint32_t vrow_off = (uint32_t)(((((vm >> 1) << 3) + vr) * VS_STRIDE + (vm & 1) * 4) * 4);
    int psrc = (lane & 28) | (fk >> 1);
    bool podd = (fk & 1) != 0;
    // K ldmatrix offsets: x4 -> d-groups 0..3 (16B each); x2 -> d-groups 4,5
    uint32_t kx4_off = (uint32_t)(g * 16);
    uint32_t kx2_off = (uint32_t)(64 + ((lane >> 3) & 1) * 16);

    for (int c = 0; c < 49; c++) {
        if (c >= 47) { CP_WAIT0(); } else { CP_WAIT1(); }
        __syncthreads();

        if (c + 2 < 49)
            attn_fill(sm_sh, tid, kbase, vbase, c + 2, (c + 2) % 3);

        uint32_t kb_sh = sm_sh + (uint32_t)(((c % 3) * STAGEW) * 4);
        uint32_t vb_sh = kb_sh + (uint32_t)(KS_BUFW * 4) + vrow_off;

        for (int sub = 0; sub < 8; sub++) {
            // ---- QK (bf16): 2 ldmatrix + 3 mma ----
            float s0[4] = {0.f, 0.f, 0.f, 0.f};
            uint32_t krow = kb_sh + (uint32_t)((sub * 8 + lr) * KS_STRIDEB);
            unsigned kb4[4], kb2[2];
            ldsm_x4(kb4[0], kb4[1], kb4[2], kb4[3], krow + kx4_off);
            ldsm_x2(kb2[0], kb2[1], krow + kx2_off);
            mma_bf16(s0, qf[0], kb4);
            mma_bf16(s0, qf[1], kb4 + 2);
            mma_bf16(s0, qf[2], kb2);
            // ---- exp (tf32) + lsum ----
            unsigned c0 = f2tf32(__expf(s0[0]));
            unsigned c1 = f2tf32(__expf(s0[1]));
            unsigned c2 = f2tf32(__expf(s0[2]));
            unsigned c3 = f2tf32(__expf(s0[3]));
            lsum[0] += __uint_as_float(c0) + __uint_as_float(c1);
            lsum[1] += __uint_as_float(c2) + __uint_as_float(c3);
            // ---- P C-frag -> A-frag via shuffles ----
            unsigned u0 = __shfl_sync(0xffffffffu, c0, psrc);
            unsigned u1 = __shfl_sync(0xffffffffu, c1, psrc);
            unsigned u2 = __shfl_sync(0xffffffffu, c2, psrc);
            unsigned u3 = __shfl_sync(0xffffffffu, c3, psrc);
            unsigned w0 = __shfl_sync(0xffffffffu, c0, psrc + 2);
            unsigned w1 = __shfl_sync(0xffffffffu, c1, psrc + 2);
            unsigned w2 = __shfl_sync(0xffffffffu, c2, psrc + 2);
            unsigned w3 = __shfl_sync(0xffffffffu, c3, psrc + 2);
            unsigned pa[4];
            pa[0] = podd ? u1 : u0;
            pa[1] = podd ? u3 : u2;
            pa[2] = podd ? w1 : w0;
            pa[3] = podd ? w3 : w2;
            // ---- PV (tf32): V-frags via ldmatrix on transposed V [d][key] ----
            uint32_t vaddr = vb_sh + (uint32_t)(sub * 32);
            #pragma unroll
            for (int p = 0; p < 3; p++) {
                unsigned v0[2], v1[2];
                ldsm_x4(v0[0], v0[1], v1[0], v1[1],
                        vaddr + (uint32_t)(p * (16 * VS_STRIDE * 4)));
                mma_tf32(oacc[2 * p], pa, v0);
                mma_tf32(oacc[2 * p + 1], pa, v1);
            }
        }
    }

    // ---- epilogue ----
    #pragma unroll
    for (int hh = 0; hh < 2; hh++) {
        float l = lsum[hh];
        l += __shfl_xor_sync(0xffffffffu, l, 1);
        l += __shfl_xor_sync(0xffffffffu, l, 2);
        float inv = 1.0f / l;
        int m = wid * 16 + fr + hh * 8;
        if (m < M_) {
            float* orow = g_ao + ((size_t)b * M_ + m) * C_ + h * DH_;
            #pragma unroll
            for (int nt = 0; nt < 6; nt++) {
                float2 val;
                val.x = rtf32(oacc[nt][hh * 2 + 0] * inv);
                val.y = rtf32(oacc[nt][hh * 2 + 1] * inv);
                *(float2*)(orow + nt * 8 + 2 * fk) = val;
            }
        }
    }
}

// ----------------------------------------------------------------- launcher
extern "C" void kernel_launch(void* const* d_in, const int* in_sizes, int n_in,
                              void* d_out, int out_size)
{
    const float* x      = (const float*)d_in[0];
    const float* qp     = (const float*)d_in[1];
    const float* kv_w   = (const float*)d_in[2];
    const float* proj_w = (const float*)d_in[3];
    const float* proj_b = (const float*)d_in[4];
    const float* ln_w   = (const float*)d_in[5];
    const float* ln_b   = (const float*)d_in[6];
    float* out = (float*)d_out;

    cudaFuncSetAttribute(attn_mma_kernel,
                         cudaFuncAttributeMaxDynamicSharedMemorySize, AT_SMEMW * 4);
    cudaFuncSetAttribute(mma_kv_kernel,
                         cudaFuncAttributeMaxDynamicSharedMemorySize, GSMEMB);
    cudaFuncSetAttribute(mma_proj_kernel,
                         cudaFuncAttributeMaxDynamicSharedMemorySize, GSMEMB);

    round_w_kernel<<<(2 * C_ * C_ + 255) / 256, 256>>>(kv_w, proj_w);

    ln_gelu_kernel<<<T_ / 8, 256>>>(x, ln_w, ln_b);

    dim3 g2(6, 784);
    mma_kv_kernel<<<g2, 256, GSMEMB>>>();

    attn_mma_kernel<<<B_ * H_, AT_THREADS, AT_SMEMW * 4>>>(qp);

    dim3 g4(3, 49);
    mma_proj_kernel<<<g4, 256, GSMEMB>>>(proj_b, out);
}

// round 17
// speedup vs baseline: 1.3782x; 1.0921x over previous
#include <cuda_runtime.h>
#include <cuda_bf16.h>
#include <math.h>
#include <stdint.h>

// Problem dims
#define B_   32
#define N_   3136
#define C_   384
#define H_   8
#define DH_  48
#define M_   196
#define T_   (B_ * N_)          // 100352 tokens

// ---------------- scratch (static device globals; no runtime allocation) ---
__device__ float g_xg[T_ * C_];                    // gelu(ln(x)), tf32-valued
__device__ __nv_bfloat16 g_xgh[T_ * C_];           // same, bf16 (for K-half GEMM)
__device__ __nv_bfloat16 g_kh[B_ * H_ * N_ * DH_]; // k [b,h,n,d] bf16
__device__ float g_v [B_ * H_ * DH_ * N_];         // v [b,h,d,n] transposed, tf32
__device__ float g_ao[B_ * M_ * C_];               // attn out [b,m,c], tf32-valued
__device__ float g_wkv[2 * C_ * C_];               // kv_w pre-rounded tf32 (V uses rows 384..767)
__device__ __nv_bfloat16 g_wkh[C_ * C_];           // kv_w K-rows (0..383) in bf16
__device__ float g_wpj[C_ * C_];                   // proj_w pre-rounded tf32

// ------------------------------------------------------ helpers
__device__ __forceinline__ unsigned f2tf32(float f) {
    unsigned r;
    asm("cvt.rna.tf32.f32 %0, %1;" : "=r"(r) : "f"(f));
    return r;
}
__device__ __forceinline__ float rtf32(float f) { return __uint_as_float(f2tf32(f)); }

__device__ __forceinline__ void mma_tf32(float* c, const unsigned* a, const unsigned* b) {
    asm volatile(
        "mma.sync.aligned.m16n8k8.row.col.f32.tf32.tf32.f32 "
        "{%0,%1,%2,%3}, {%4,%5,%6,%7}, {%8,%9}, {%0,%1,%2,%3};"
        : "+f"(c[0]), "+f"(c[1]), "+f"(c[2]), "+f"(c[3])
        : "r"(a[0]), "r"(a[1]), "r"(a[2]), "r"(a[3]),
          "r"(b[0]), "r"(b[1]));
}
__device__ __forceinline__ void mma_bf16(float* c, const unsigned* a, const unsigned* b) {
    asm volatile(
        "mma.sync.aligned.m16n8k16.row.col.f32.bf16.bf16.f32 "
        "{%0,%1,%2,%3}, {%4,%5,%6,%7}, {%8,%9}, {%0,%1,%2,%3};"
        : "+f"(c[0]), "+f"(c[1]), "+f"(c[2]), "+f"(c[3])
        : "r"(a[0]), "r"(a[1]), "r"(a[2]), "r"(a[3]),
          "r"(b[0]), "r"(b[1]));
}
__device__ __forceinline__ unsigned pack_bf16(float lo, float hi) {
    unsigned r;
    asm("cvt.rn.bf16x2.f32 %0, %1, %2;" : "=r"(r) : "f"(hi), "f"(lo));
    return r;
}

__device__ __forceinline__ void ldsm_x4(unsigned &r0, unsigned &r1,
                                        unsigned &r2, unsigned &r3, uint32_t addr) {
    asm volatile("ldmatrix.sync.aligned.m8n8.x4.shared.b16 {%0,%1,%2,%3}, [%4];"
        : "=r"(r0), "=r"(r1), "=r"(r2), "=r"(r3) : "r"(addr));
}
__device__ __forceinline__ void ldsm_x2(unsigned &r0, unsigned &r1, uint32_t addr) {
    asm volatile("ldmatrix.sync.aligned.m8n8.x2.shared.b16 {%0,%1}, [%2];"
        : "=r"(r0), "=r"(r1) : "r"(addr));
}

__device__ __forceinline__ void cp16(uint32_t sa, const void* g) {
    asm volatile("cp.async.cg.shared.global [%0], [%1], 16;" :: "r"(sa), "l"(g));
}
#define CP_COMMIT() asm volatile("cp.async.commit_group;")
#define CP_WAIT1()  asm volatile("cp.async.wait_group 1;")
#define CP_WAIT0()  asm volatile("cp.async.wait_group 0;")

// ------------------------------------------------- K0: pre-round weights
__global__ __launch_bounds__(256) void round_w_kernel(
    const float* __restrict__ kv_w, const float* __restrict__ proj_w)
{
    int i = blockIdx.x * 256 + threadIdx.x;
    if (i < 2 * C_ * C_) g_wkv[i] = rtf32(kv_w[i]);
    if (i < C_ * C_) {
        g_wpj[i] = rtf32(proj_w[i]);
        g_wkh[i] = __float2bfloat16(kv_w[i]);   // K weight rows in bf16
    }
}

// ---------------------------------------------------------------- K1: LN+GELU
__global__ __launch_bounds__(256) void ln_gelu_kernel(
    const float* __restrict__ x,
    const float* __restrict__ lw,
    const float* __restrict__ lb)
{
    int t = (blockIdx.x * 256 + threadIdx.x) >> 5;
    int lane = threadIdx.x & 31;
    const float4* xr = (const float4*)(x + (size_t)t * C_);
    float4* outr = (float4*)(g_xg + (size_t)t * C_);
    __nv_bfloat162* outh = (__nv_bfloat162*)(g_xgh + (size_t)t * C_);

    float4 a = xr[lane], bq = xr[lane + 32], cq = xr[lane + 64];
    float s = a.x + a.y + a.z + a.w + bq.x + bq.y + bq.z + bq.w
            + cq.x + cq.y + cq.z + cq.w;
    float q = a.x*a.x + a.y*a.y + a.z*a.z + a.w*a.w
            + bq.x*bq.x + bq.y*bq.y + bq.z*bq.z + bq.w*bq.w
            + cq.x*cq.x + cq.y*cq.y + cq.z*cq.z + cq.w*cq.w;
    #pragma unroll
    for (int o = 16; o > 0; o >>= 1) {
        s += __shfl_xor_sync(0xffffffffu, s, o);
        q += __shfl_xor_sync(0xffffffffu, q, o);
    }
    float mu  = s * (1.0f / C_);
    float var = q * (1.0f / C_) - mu * mu;
    float rs  = rsqrtf(var + 1e-6f);

    const float4* lw4 = (const float4*)lw;
    const float4* lb4 = (const float4*)lb;
    #pragma unroll
    for (int j = 0; j < 3; j++) {
        float4 v = (j == 0) ? a : ((j == 1) ? bq : cq);
        float4 w = lw4[lane + j * 32];
        float4 bb = lb4[lane + j * 32];
        float4 o;
        float y;
        y = (v.x - mu) * rs * w.x + bb.x;
        o.x = rtf32(0.5f * y * (1.0f + erff(y * 0.70710678118654752f)));
        y = (v.y - mu) * rs * w.y + bb.y;
        o.y = rtf32(0.5f * y * (1.0f + erff(y * 0.70710678118654752f)));
        y = (v.z - mu) * rs * w.z + bb.z;
        o.z = rtf32(0.5f * y * (1.0f + erff(y * 0.70710678118654752f)));
        y = (v.w - mu) * rs * w.w + bb.w;
        o.w = rtf32(0.5f * y * (1.0f + erff(y * 0.70710678118654752f)));
        outr[lane + j * 32] = o;
        __nv_bfloat162 h0, h1;
        h0.x = __float2bfloat16(o.x); h0.y = __float2bfloat16(o.y);
        h1.x = __float2bfloat16(o.z); h1.y = __float2bfloat16(o.w);
        outh[(lane + j * 32) * 2]     = h0;
        outh[(lane + j * 32) * 2 + 1] = h1;
    }
}

// ====================== K2a: K-half GEMM in bf16 (m16n8k16) =================
// out[t, c] = sum xgh[t,:]*wkh[c,:], c<384. CTA 128x128, chunk k=32 (2 kp16),
// A,B bf16 [row][k-pair] stride 20 words (R12-validated bank pattern).
#define KH_STRIDE 20
#define KH_STAGEW (128 * KH_STRIDE)    // 2560 words
#define KH_BOFF   (3 * KH_STAGEW)
#define KH_SMEMB  (6 * KH_STAGEW * 4)  // 61440 B

__device__ __forceinline__ void kh_cp_chunk(
    uint32_t sm_sh, int tid, const __nv_bfloat16* Ab, const __nv_bfloat16* Bb, int c, int stage)
{
    uint32_t as = sm_sh + (uint32_t)(stage * KH_STAGEW * 4);
    uint32_t bs = sm_sh + (uint32_t)((KH_BOFF + stage * KH_STAGEW) * 4);
    #pragma unroll
    for (int j = 0; j < 2; j++) {
        int cidx = tid + j * 256;         // 0..511
        int row = cidx >> 2, u = cidx & 3;  // 4 x 16B units (8 bf16) per row
        cp16(as + (uint32_t)((row * KH_STRIDE + u * 4) * 4),
             Ab + (size_t)row * C_ + c * 32 + u * 8);
        cp16(bs + (uint32_t)((row * KH_STRIDE + u * 4) * 4),
             Bb + (size_t)row * C_ + c * 32 + u * 8);
    }
    CP_COMMIT();
}

__global__ void __launch_bounds__(256, 2) mma_k_kernel()
{
    extern __shared__ float sm[];
    uint32_t sm_sh = (uint32_t)__cvta_generic_to_shared(sm);
    int n0 = blockIdx.x * 128;        // 0..256 (K region)
    int m0 = blockIdx.y * 128;
    int tid = threadIdx.x;
    int wid = tid >> 5, lane = tid & 31;
    int wm = wid >> 2, wn = wid & 3;
    int fr = lane >> 2, fk = lane & 3;

    const __nv_bfloat16* Ab = g_xgh + (size_t)m0 * C_;
    const __nv_bfloat16* Bb = g_wkh + (size_t)n0 * C_;

    float acc[4][4][4];
    #pragma unroll
    for (int i = 0; i < 4; i++)
        #pragma unroll
        for (int j = 0; j < 4; j++)
            #pragma unroll
            for (int r = 0; r < 4; r++) acc[i][j][r] = 0.0f;

    kh_cp_chunk(sm_sh, tid, Ab, Bb, 0, 0);
    kh_cp_chunk(sm_sh, tid, Ab, Bb, 1, 1);

    for (int c = 0; c < 12; c++) {
        if (c >= 10) { CP_WAIT0(); } else { CP_WAIT1(); }
        __syncthreads();
        const unsigned* As = (const unsigned*)(sm + (c % 3) * KH_STAGEW);
        const unsigned* Bs = (const unsigned*)(sm + KH_BOFF + (c % 3) * KH_STAGEW);

        #pragma unroll
        for (int j = 0; j < 2; j++) {           // two kp16 groups per chunk32
            int kp = j * 8;                     // word (bf16-pair) offset
            unsigned af[4][4];
            #pragma unroll
            for (int mt = 0; mt < 4; mt++) {
                int rb = wm * 64 + mt * 16 + fr;
                af[mt][0] = As[rb * KH_STRIDE + kp + fk];
                af[mt][1] = As[(rb + 8) * KH_STRIDE + kp + fk];
                af[mt][2] = As[rb * KH_STRIDE + kp + fk + 4];
                af[mt][3] = As[(rb + 8) * KH_STRIDE + kp + fk + 4];
            }
            unsigned bf[4][2];
            #pragma unroll
            for (int nt = 0; nt < 4; nt++) {
                int cb = wn * 32 + nt * 8 + fr;
                bf[nt][0] = Bs[cb * KH_STRIDE + kp + fk];
                bf[nt][1] = Bs[cb * KH_STRIDE + kp + fk + 4];
            }
            #pragma unroll
            for (int mt = 0; mt < 4; mt++)
                #pragma unroll
                for (int nt = 0; nt < 4; nt++)
                    mma_bf16(acc[mt][nt], af[mt], bf[nt]);
        }

        if (c + 2 < 12)
            kh_cp_chunk(sm_sh, tid, Ab, Bb, c + 2, (c + 2) % 3);
    }

    #pragma unroll
    for (int mt = 0; mt < 4; mt++) {
        #pragma unroll
        for (int half = 0; half < 2; half++) {
            int r  = m0 + wm * 64 + mt * 16 + fr + half * 8;
            int bb = r / N_;
            int nn = r - bb * N_;
            #pragma unroll
            for (int nt = 0; nt < 4; nt++) {
                int c = n0 + wn * 32 + nt * 8 + fk * 2;
                int h = c / DH_;
                int d = c - h * DH_;
                __nv_bfloat162 kv2;
                kv2.x = __float2bfloat16(acc[mt][nt][half * 2 + 0]);
                kv2.y = __float2bfloat16(acc[mt][nt][half * 2 + 1]);
                *(__nv_bfloat162*)(g_kh + (((size_t)bb * H_ + h) * N_ + nn) * DH_ + d) = kv2;
            }
        }
    }
}

// ============= shared 3-stage pipelined tf32 GEMM core (chunk 32) ===========
#define GSTRIDE 36
#define GSTAGEW (128 * GSTRIDE)
#define GBOFF   (3 * GSTAGEW)
#define GSMEMB  (6 * GSTAGEW * 4)    // 110592 bytes

__device__ __forceinline__ void gemm_cp_chunk(
    float* sm, int stage, int tid, const float* Abase, const float* Bbase, int c)
{
    float* as = sm + stage * GSTAGEW;
    float* bs = sm + GBOFF + stage * GSTAGEW;
    #pragma unroll
    for (int j = 0; j < 4; j++) {
        int cidx = tid + j * 256;
        int row = cidx >> 3, kq = cidx & 7;
        cp16((uint32_t)__cvta_generic_to_shared(as + row * GSTRIDE + kq * 4),
             Abase + (size_t)row * C_ + c * 32 + kq * 4);
        cp16((uint32_t)__cvta_generic_to_shared(bs + row * GSTRIDE + kq * 4),
             Bbase + (size_t)row * C_ + c * 32 + kq * 4);
    }
    CP_COMMIT();
}

__device__ __forceinline__ void gemm_mainloop(
    float* sm, int tid, const float* Abase, const float* Bbase,
    float acc[4][4][4], int wm, int wn, int fr, int fk)
{
    gemm_cp_chunk(sm, 0, tid, Abase, Bbase, 0);
    gemm_cp_chunk(sm, 1, tid, Abase, Bbase, 1);

    for (int c = 0; c < 12; c++) {
        if (c >= 10) { CP_WAIT0(); } else { CP_WAIT1(); }
        __syncthreads();
        const unsigned* As = (const unsigned*)(sm + (c % 3) * GSTAGEW);
        const unsigned* Bs = (const unsigned*)(sm + GBOFF + (c % 3) * GSTAGEW);

        #pragma unroll
        for (int kp = 0; kp < 32; kp += 8) {
            unsigned af[4][4];
            #pragma unroll
            for (int mt = 0; mt < 4; mt++) {
                int rb = wm * 64 + mt * 16 + fr;
                af[mt][0] = As[rb * GSTRIDE + kp + fk];
                af[mt][1] = As[(rb + 8) * GSTRIDE + kp + fk];
                af[mt][2] = As[rb * GSTRIDE + kp + fk + 4];
                af[mt][3] = As[(rb + 8) * GSTRIDE + kp + fk + 4];
            }
            unsigned bf[4][2];
            #pragma unroll
            for (int nt = 0; nt < 4; nt++) {
                int cb = wn * 32 + nt * 8 + fr;
                bf[nt][0] = Bs[cb * GSTRIDE + kp + fk];
                bf[nt][1] = Bs[cb * GSTRIDE + kp + fk + 4];
            }
            #pragma unroll
            for (int mt = 0; mt < 4; mt++)
                #pragma unroll
                for (int nt = 0; nt < 4; nt++)
                    mma_tf32(acc[mt][nt], af[mt], bf[nt]);
        }

        if (c + 2 < 12)
            gemm_cp_chunk(sm, (c + 2) % 3, tid, Abase, Bbase, c + 2);
    }
}

// ------------------------------------------- K2b: V-half GEMM (tf32, as R15)
__global__ void __launch_bounds__(256, 2) mma_v_kernel()
{
    extern __shared__ float sm[];
    int n0 = blockIdx.x * 128;            // 0..256 within V region
    int m0 = blockIdx.y * 128;
    int tid = threadIdx.x;
    int wid = tid >> 5, lane = tid & 31;
    int wm = wid >> 2, wn = wid & 3;
    int fr = lane >> 2, fk = lane & 3;

    float acc[4][4][4];
    #pragma unroll
    for (int i = 0; i < 4; i++)
        #pragma unroll
        for (int j = 0; j < 4; j++)
            #pragma unroll
            for (int r = 0; r < 4; r++) acc[i][j][r] = 0.0f;

    gemm_mainloop(sm, tid, g_xg + (size_t)m0 * C_,
                  g_wkv + (size_t)(C_ + n0) * C_, acc, wm, wn, fr, fk);

    #pragma unroll
    for (int mt = 0; mt < 4; mt++) {
        #pragma unroll
        for (int half = 0; half < 2; half++) {
            int r  = m0 + wm * 64 + mt * 16 + fr + half * 8;
            int bb = r / N_;
            int nn = r - bb * N_;
            #pragma unroll
            for (int nt = 0; nt < 4; nt++) {
                int cc = n0 + wn * 32 + nt * 8 + fk * 2;
                int h  = cc / DH_;
                int d  = cc - h * DH_;
                float* dst = g_v + (((size_t)bb * H_ + h) * DH_ + d) * N_ + nn;
                dst[0]  = rtf32(acc[mt][nt][half * 2 + 0]);
                dst[N_] = rtf32(acc[mt][nt][half * 2 + 1]);
            }
        }
    }
}

// -------------------------------------------------------------- K4: proj GEMM
__global__ void __launch_bounds__(256, 2) mma_proj_kernel(
    const float* __restrict__ bias,
    float* __restrict__ out)
{
    extern __shared__ float sm[];
    int n0 = blockIdx.x * 128;
    int m0 = blockIdx.y * 128;
    int tid = threadIdx.x;
    int wid = tid >> 5, lane = tid & 31;
    int wm = wid >> 2, wn = wid & 3;
    int fr = lane >> 2, fk = lane & 3;

    float acc[4][4][4];
    #pragma unroll
    for (int i = 0; i < 4; i++)
        #pragma unroll
        for (int j = 0; j < 4; j++)
            #pragma unroll
            for (int r = 0; r < 4; r++) acc[i][j][r] = 0.0f;

    gemm_mainloop(sm, tid, g_ao + (size_t)m0 * C_, g_wpj + (size_t)n0 * C_,
                  acc, wm, wn, fr, fk);

    #pragma unroll
    for (int mt = 0; mt < 4; mt++) {
        #pragma unroll
        for (int half = 0; half < 2; half++) {
            int r = m0 + wm * 64 + mt * 16 + fr + half * 8;
            #pragma unroll
            for (int nt = 0; nt < 4; nt++) {
                int c = n0 + wn * 32 + nt * 8 + fk * 2;
                float2 val;
                val.x = acc[mt][nt][half * 2 + 0] + bias[c];
                val.y = acc[mt][nt][half * 2 + 1] + bias[c + 1];
                *(float2*)(out + (size_t)r * C_ + c) = val;
            }
        }
    }
}

// ------------------------------------------------------------- K3: MMA attn
// (R16-validated: bf16 QK, tf32 PV, 13 warps, triple-buffered ring.)
#define AT_THREADS 416
#define QROWS 208
#define QS_STRIDE 52
#define KS_STRIDEB 112
#define KS_BUFW 1792
#define VS_STRIDE 68
#define VS_BUFW 3264
#define STAGEW  (KS_BUFW + VS_BUFW)
#define AT_SMEMW (3 * STAGEW)

__device__ __forceinline__ void attn_fill(
    uint32_t sm_sh, int tid, const __nv_bfloat16* kbase, const float* vbase,
    int c, int s)
{
    uint32_t stb = sm_sh + (uint32_t)(s * STAGEW * 4);
    const __nv_bfloat16* ks = kbase + (size_t)c * 64 * DH_;
    for (int cidx = tid; cidx < 384; cidx += AT_THREADS) {
        int r = cidx / 6, u = cidx - r * 6;
        cp16(stb + (uint32_t)(r * KS_STRIDEB + u * 16), ks + r * DH_ + u * 8);
    }
    const float* vsb = vbase + c * 64;
    for (int cidx = tid; cidx < 768; cidx += AT_THREADS) {
        int d = cidx >> 4, u = cidx & 15;
        cp16(stb + (uint32_t)((KS_BUFW + d * VS_STRIDE + u * 4) * 4),
             vsb + (size_t)d * N_ + u * 4);
    }
    CP_COMMIT();
}

__global__ void __launch_bounds__(AT_THREADS, 2) attn_mma_kernel(const float* __restrict__ qp)
{
    extern __shared__ uint32_t smv[];
    int tid = threadIdx.x;
    int bh = blockIdx.x;
    int b = bh >> 3, h = bh & 7;
    int wid = tid >> 5, lane = tid & 31;
    int fr = lane >> 2, fk = lane & 3;
    int g = lane >> 3, lr = lane & 7;

    const __nv_bfloat16* kbase = g_kh + (size_t)bh * N_ * DH_;
    const float* vbase = g_v + (size_t)bh * DH_ * N_;

    float* smf = (float*)smv;
    for (int idx = tid; idx < QROWS * 48; idx += AT_THREADS) {
        int m = idx / 48, d = idx - m * 48;
        smf[m * QS_STRIDE + d] = (m < M_) ? qp[((size_t)m * H_ + h) * DH_ + d] : 0.0f;
    }
    __syncthreads();

    unsigned qf[3][4];
    {
        int r0 = wid * 16 + fr;
        #pragma unroll
        for (int kt = 0; kt < 3; kt++) {
            int d0 = 16 * kt + 2 * fk;
            qf[kt][0] = pack_bf16(smf[r0 * QS_STRIDE + d0],       smf[r0 * QS_STRIDE + d0 + 1]);
            qf[kt][1] = pack_bf16(smf[(r0 + 8) * QS_STRIDE + d0], smf[(r0 + 8) * QS_STRIDE + d0 + 1]);
            qf[kt][2] = pack_bf16(smf[r0 * QS_STRIDE + d0 + 8],   smf[r0 * QS_STRIDE + d0 + 9]);
            qf[kt][3] = pack_bf16(smf[(r0 + 8) * QS_STRIDE + d0 + 8], smf[(r0 + 8) * QS_STRIDE + d0 + 9]);
        }
    }
    __syncthreads();

    uint32_t sm_sh = (uint32_t)__cvta_generic_to_shared(smv);

    attn_fill(sm_sh, tid, kbase, vbase, 0, 0);
    attn_fill(sm_sh, tid, kbase, vbase, 1, 1);

    float oacc[6][4];
    #pragma unroll
    for (int j = 0; j < 6; j++)
        #pragma unroll
        for (int r = 0; r < 4; r++) oacc[j][r] = 0.0f;
    float lsum[2] = {0.f, 0.f};

    int vm = lane >> 3, vr = lane & 7;
    uint32_t vrow_off = (uint32_t)(((((vm >> 1) << 3) + vr) * VS_STRIDE + (vm & 1) * 4) * 4);
    int psrc = (lane & 28) | (fk >> 1);
    bool podd = (fk & 1) != 0;
    uint32_t kx4_off = (uint32_t)(g * 16);
    uint32_t kx2_off = (uint32_t)(64 + ((lane >> 3) & 1) * 16);

    for (int c = 0; c < 49; c++) {
        if (c >= 47) { CP_WAIT0(); } else { CP_WAIT1(); }
        __syncthreads();

        if (c + 2 < 49)
            attn_fill(sm_sh, tid, kbase, vbase, c + 2, (c + 2) % 3);

        uint32_t kb_sh = sm_sh + (uint32_t)(((c % 3) * STAGEW) * 4);
        uint32_t vb_sh = kb_sh + (uint32_t)(KS_BUFW * 4) + vrow_off;

        for (int sub = 0; sub < 8; sub++) {
            float s0[4] = {0.f, 0.f, 0.f, 0.f};
            uint32_t krow = kb_sh + (uint32_t)((sub * 8 + lr) * KS_STRIDEB);
            unsigned kb4[4], kb2[2];
            ldsm_x4(kb4[0], kb4[1], kb4[2], kb4[3], krow + kx4_off);
            ldsm_x2(kb2[0], kb2[1], krow + kx2_off);
            mma_bf16(s0, qf[0], kb4);
            mma_bf16(s0, qf[1], kb4 + 2);
            mma_bf16(s0, qf[2], kb2);
            unsigned c0 = f2tf32(__expf(s0[0]));
            unsigned c1 = f2tf32(__expf(s0[1]));
            unsigned c2 = f2tf32(__expf(s0[2]));
            unsigned c3 = f2tf32(__expf(s0[3]));
            lsum[0] += __uint_as_float(c0) + __uint_as_float(c1);
            lsum[1] += __uint_as_float(c2) + __uint_as_float(c3);
            unsigned u0 = __shfl_sync(0xffffffffu, c0, psrc);
            unsigned u1 = __shfl_sync(0xffffffffu, c1, psrc);
            unsigned u2 = __shfl_sync(0xffffffffu, c2, psrc);
            unsigned u3 = __shfl_sync(0xffffffffu, c3, psrc);
            unsigned w0 = __shfl_sync(0xffffffffu, c0, psrc + 2);
            unsigned w1 = __shfl_sync(0xffffffffu, c1, psrc + 2);
            unsigned w2 = __shfl_sync(0xffffffffu, c2, psrc + 2);
            unsigned w3 = __shfl_sync(0xffffffffu, c3, psrc + 2);
            unsigned pa[4];
            pa[0] = podd ? u1 : u0;
            pa[1] = podd ? u3 : u2;
            pa[2] = podd ? w1 : w0;
            pa[3] = podd ? w3 : w2;
            uint32_t vaddr = vb_sh + (uint32_t)(sub * 32);
            #pragma unroll
            for (int p = 0; p < 3; p++) {
                unsigned v0[2], v1[2];
                ldsm_x4(v0[0], v0[1], v1[0], v1[1],
                        vaddr + (uint32_t)(p * (16 * VS_STRIDE * 4)));
                mma_tf32(oacc[2 * p], pa, v0);
                mma_tf32(oacc[2 * p + 1], pa, v1);
            }
        }
    }

    #pragma unroll
    for (int hh = 0; hh < 2; hh++) {
        float l = lsum[hh];
        l += __shfl_xor_sync(0xffffffffu, l, 1);
        l += __shfl_xor_sync(0xffffffffu, l, 2);
        float inv = 1.0f / l;
        int m = wid * 16 + fr + hh * 8;
        if (m < M_) {
            float* orow = g_ao + ((size_t)b * M_ + m) * C_ + h * DH_;
            #pragma unroll
            for (int nt = 0; nt < 6; nt++) {
                float2 val;
                val.x = rtf32(oacc[nt][hh * 2 + 0] * inv);
                val.y = rtf32(oacc[nt][hh * 2 + 1] * inv);
                *(float2*)(orow + nt * 8 + 2 * fk) = val;
            }
        }
    }
}

// ----------------------------------------------------------------- launcher
extern "C" void kernel_launch(void* const* d_in, const int* in_sizes, int n_in,
                              void* d_out, int out_size)
{
    const float* x      = (const float*)d_in[0];
    const float* qp     = (const float*)d_in[1];
    const float* kv_w   = (const float*)d_in[2];
    const float* proj_w = (const float*)d_in[3];
    const float* proj_b = (const float*)d_in[4];
    const float* ln_w   = (const float*)d_in[5];
    const float* ln_b   = (const float*)d_in[6];
    float* out = (float*)d_out;

    cudaFuncSetAttribute(attn_mma_kernel,
                         cudaFuncAttributeMaxDynamicSharedMemorySize, AT_SMEMW * 4);
    cudaFuncSetAttribute(mma_k_kernel,
                         cudaFuncAttributeMaxDynamicSharedMemorySize, KH_SMEMB);
    cudaFuncSetAttribute(mma_v_kernel,
                         cudaFuncAttributeMaxDynamicSharedMemorySize, GSMEMB);
    cudaFuncSetAttribute(mma_proj_kernel,
                         cudaFuncAttributeMaxDynamicSharedMemorySize, GSMEMB);

    round_w_kernel<<<(2 * C_ * C_ + 255) / 256, 256>>>(kv_w, proj_w);

    ln_gelu_kernel<<<T_ / 8, 256>>>(x, ln_w, ln_b);

    dim3 gk(3, 784);
    mma_k_kernel<<<gk, 256, KH_SMEMB>>>();

    dim3 gv(3, 784);
    mma_v_kernel<<<gv, 256, GSMEMB>>>();

    attn_mma_kernel<<<B_ * H_, AT_THREADS, AT_SMEMW * 4>>>(qp);

    dim3 g4(3, 49);
    mma_proj_kernel<<<g4, 256, GSMEMB>>>(proj_b, out);
}